// round 11
// baseline (speedup 1.0000x reference)
#include <cuda_runtime.h>
#include <cuda_bf16.h>
#include <math.h>
#include <cub/block/block_radix_sort.cuh>

// ---------------- problem constants ----------------
#define N0 4096
#define N1 2048
#define N2 1024
#define N3 512
#define NE 65536
#define FH 64
#define FO 128
#define MAXD0 128
#define MAXD1 2048

// ---------------- static device scratch ----------------
__device__ unsigned char g_A0b[(size_t)N0*N0];
__device__ int   g_idx0[(size_t)N0*MAXD0]; __device__ float g_val0[(size_t)N0*MAXD0]; __device__ int g_cnt0[N0];
__device__ int   g_idx1[(size_t)N1*MAXD1]; __device__ float g_val1[(size_t)N1*MAXD1]; __device__ int g_cnt1[N1];
__device__ float g_A2d[(size_t)N2*N2];
__device__ float g_A3d[(size_t)N3*N3];
__device__ float g_Rg[(size_t)N3*N2];
__device__ float g_Cg[(size_t)N2*N3];
__device__ float g_part[1<<20];
__device__ float g_Y[(size_t)N0*FO];
__device__ float g_S[(size_t)N0*FO];
__device__ float g_x0[N0*FH], g_x1[N1*FH], g_x2[N2*FH], g_x3[N3*FH];
__device__ float g_hbuf[N0*FH];
__device__ float g_up[N1*FH];
__device__ float g_U[N0*FO];
__device__ float g_res[N0*FO];
__device__ float g_feat1[(size_t)N0*512];
__device__ float g_gout[(size_t)N0*512];
__device__ float g_dinv0[N0], g_dfix0[N0];
__device__ float g_dinv1[N1], g_dinv2[N2], g_dinv3[N3];
__device__ int   g_perm1[N1]; __device__ float g_vals1[N1];
__device__ int   g_perm2[N2]; __device__ float g_vals2[N2];
__device__ int   g_perm3[N3]; __device__ float g_vals3[N3];
__device__ int   g_ipos1[N0], g_ipos2[N1], g_ipos3[N2];
__device__ float g_es[N0*4], g_ed[N0*4];

static inline int cdiv(int a,int b){return (a+b-1)/b;}

// ---------------- gemmBig: 64x64x16, TM=TN=4, optional split-K, optional B row-scale ----------------
template<int BSCALE>
__global__ void __launch_bounds__(256)
gemmBig(int M,int N,int K,int KS,const float* __restrict__ A,const float* __restrict__ B,
        float* __restrict__ dest,const float* __restrict__ bs){
    __shared__ __align__(16) float As[16][64];
    __shared__ __align__(16) float Bs[16][64];
    const int bm=blockIdx.y*64, bn=blockIdx.x*64, z=blockIdx.z;
    const int tid=threadIdx.x;
    const int trow=tid/16, tcol=tid%16;
    const int kchunk=K/KS;
    const int kbeg=z*kchunk, kend=kbeg+kchunk;
    float acc[4][4];
    #pragma unroll
    for(int i=0;i<4;i++)
        #pragma unroll
        for(int j=0;j<4;j++) acc[i][j]=0.f;

    for(int k0=kbeg;k0<kend;k0+=16){
        {
            int m=tid/4, kq=tid%4;
            float4 v=*(const float4*)(A+(size_t)(bm+m)*K+k0+kq*4);
            As[kq*4+0][m]=v.x; As[kq*4+1][m]=v.y; As[kq*4+2][m]=v.z; As[kq*4+3][m]=v.w;
        }
        {
            int k=tid/16, nq=tid%16;
            float4 v=*(const float4*)(B+(size_t)(k0+k)*N+bn+nq*4);
            if(BSCALE){
                float s=bs[k0+k];
                v.x*=s; v.y*=s; v.z*=s; v.w*=s;
            }
            *(float4*)&Bs[k][nq*4]=v;
        }
        __syncthreads();
        #pragma unroll
        for(int kk=0;kk<16;kk++){
            float4 ra=*(const float4*)&As[kk][trow*4];
            float4 rb=*(const float4*)&Bs[kk][tcol*4];
            float a[4]={ra.x,ra.y,ra.z,ra.w};
            float b[4]={rb.x,rb.y,rb.z,rb.w};
            #pragma unroll
            for(int i=0;i<4;i++)
                #pragma unroll
                for(int j=0;j<4;j++) acc[i][j]+=a[i]*b[j];
        }
        __syncthreads();
    }
    float* out=dest+(size_t)z*M*N;
    #pragma unroll
    for(int i=0;i<4;i++){
        int gm=bm+trow*4+i;
        #pragma unroll
        for(int j=0;j<4;j++){
            out[(size_t)gm*N+bn+tcol*4+j]=acc[i][j];
        }
    }
}

// split-K reduce + GCN epilogue (raw Y): v = di*acc + 2*di*di*Y + b
__global__ void k_kred_gcn(int n,int f,int KS,const float* __restrict__ part,
                           const float* __restrict__ Y,const float* __restrict__ di,
                           const float* __restrict__ b,float* __restrict__ out,int relu){
    int t=blockIdx.x*blockDim.x+threadIdx.x;
    if(t>=n*f) return;
    float acc=0.f;
    for(int z=0;z<KS;z++) acc+=part[(size_t)z*n*f+t];
    int r=t/f;
    float d=di[r];
    float v=d*acc + 2.f*d*d*Y[t] + b[t%f];
    out[t]= relu? fmaxf(v,0.f) : v;
}

// A3 split-K reduce (KS=4) + zero diag + rowsum -> dinv3
__global__ void __launch_bounds__(256) k_finishA3red(const float* __restrict__ part,
                                                     float* __restrict__ A3,float* __restrict__ dinv){
    __shared__ float red[8];
    int r=blockIdx.x, t=threadIdx.x;
    float s=0.f;
    for(int j=t;j<N3;j+=256){
        float acc=part[(size_t)0*N3*N3 + r*N3 + j]
                 +part[(size_t)1*N3*N3 + r*N3 + j]
                 +part[(size_t)2*N3*N3 + r*N3 + j]
                 +part[(size_t)3*N3*N3 + r*N3 + j];
        if(j==r) acc=0.f;
        A3[(size_t)r*N3+j]=acc;
        s+=acc;
    }
    #pragma unroll
    for(int o=16;o;o>>=1) s+=__shfl_xor_sync(0xffffffffu,s,o);
    if((t&31)==0) red[t>>5]=s;
    __syncthreads();
    if(t==0){
        float ss=0.f;
        #pragma unroll
        for(int w=0;w<8;w++) ss+=red[w];
        dinv[r]=rsqrtf(ss+2.f);
    }
}

// ---------------- gemm16: 16x64x16, TM=1,TN=4 ----------------
template<int MERGE>
__global__ void __launch_bounds__(256)
gemm16(int M,int N,int K,const float* __restrict__ Af,const float* __restrict__ B,
       float* __restrict__ C,const int* __restrict__ ipos,const float* __restrict__ xs){
    __shared__ __align__(16) float As[16][16];
    __shared__ __align__(16) float Bs[16][64];
    const int bm=blockIdx.y*16, bn=blockIdx.x*64;
    const int tid=threadIdx.x;
    const int trow=tid/16, tcol=tid%16;
    float acc[4]={0.f,0.f,0.f,0.f};
    for(int k0=0;k0<K;k0+=16){
        {
            int m=tid/16, k=tid%16;
            int gm=bm+m, gk=k0+k;
            float a=Af[(size_t)gm*K+gk];
            if(MERGE){ int j=ipos[gm]; if(j>=0) a+=xs[(size_t)j*K+gk]; }
            As[k][m]=a;
        }
        {
            int k=tid/16, nq=tid%16;
            *(float4*)&Bs[k][nq*4] = *(const float4*)(B+(size_t)(k0+k)*N+bn+nq*4);
        }
        __syncthreads();
        #pragma unroll
        for(int kk=0;kk<16;kk++){
            float a=As[kk][trow];
            float4 rb=*(const float4*)&Bs[kk][tcol*4];
            acc[0]+=a*rb.x; acc[1]+=a*rb.y; acc[2]+=a*rb.z; acc[3]+=a*rb.w;
        }
        __syncthreads();
    }
    int gm=bm+trow;
    #pragma unroll
    for(int j=0;j<4;j++)
        C[(size_t)gm*N+bn+tcol*4+j]=acc[j];
}

// ---------------- graph build ----------------
__global__ void k_buildA0(const int* __restrict__ ei, unsigned int* __restrict__ Aw){
    int e = blockIdx.x*blockDim.x+threadIdx.x;
    if(e<NE){
        int s=ei[e];
        int d=ei[NE+e];
        size_t byteoff=(size_t)d*N0+s;
        atomicAdd(&Aw[byteoff>>2], 1u<<((s&3)*8));
    }
}

__global__ void k_csr0(const unsigned char* __restrict__ Ab,int* __restrict__ idx,float* __restrict__ val,
                       int* __restrict__ cnt,float* __restrict__ dinv,float* __restrict__ dfix){
    int w=(blockIdx.x*blockDim.x+threadIdx.x)>>5;
    int lane=threadIdx.x&31;
    if(w>=N0) return;
    const unsigned int* row=(const unsigned int*)(Ab+(size_t)w*N0);
    int c=0; float rs=0.f;
    for(int base=0;base<N0/4;base+=32){
        unsigned int wv=row[base+lane];
        int colbase=(base+lane)*4;
        #pragma unroll
        for(int b=0;b<4;b++){
            int v=(wv>>(8*b))&255;
            int col=colbase+b;
            bool p=(v!=0)||(col==w);
            unsigned m=__ballot_sync(0xffffffffu,p);
            if(p){
                int off=c+__popc(m&((1u<<lane)-1u));
                idx[(size_t)w*MAXD0+off]=col;
                val[(size_t)w*MAXD0+off]=(float)v;
                rs+=(float)v;
            }
            c+=__popc(m);
        }
    }
    #pragma unroll
    for(int o=16;o;o>>=1) rs+=__shfl_xor_sync(0xffffffffu,rs,o);
    if(lane==0){
        float d=(float)Ab[(size_t)w*N0+w];
        float fx=(d==0.f)?2.f:0.f;
        cnt[w]=c;
        dfix[w]=fx;
        dinv[w]=rsqrtf(rs+fx);
    }
}

// ---------------- level0 fused SpMM ----------------
__global__ void __launch_bounds__(256) k_spmm0(const int* __restrict__ idx,const float* __restrict__ val,
                        const int* __restrict__ cnt,const float* __restrict__ dinv,
                        const float* __restrict__ dfix,
                        const float* __restrict__ x,const float* __restrict__ w,
                        const float* __restrict__ b,float* __restrict__ out){
    __shared__ float sw[3*FH];
    if(threadIdx.x<3*FH) sw[threadIdx.x]=w[threadIdx.x];
    __syncthreads();
    int r = blockIdx.x*4 + threadIdx.x/FH;
    int c = threadIdx.x%FH;
    int cn=cnt[r];
    const int* ip=idx+(size_t)r*MAXD0;
    const float* vp=val+(size_t)r*MAXD0;
    float w0c=sw[c], w1c=sw[FH+c], w2c=sw[2*FH+c];
    float acc=0.f;
    for(int e=0;e<cn;e++){
        int s=ip[e];
        const float* xr=x+(size_t)s*3;
        float ys=dinv[s]*(xr[0]*w0c+xr[1]*w1c+xr[2]*w2c);
        acc += vp[e]*ys;
    }
    float di=dinv[r];
    const float* xr=x+(size_t)r*3;
    float ysS=di*(xr[0]*w0c+xr[1]*w1c+xr[2]*w2c);
    float v = di*acc + dfix[r]*di*ysS + b[c];
    out[(size_t)r*FH+c]=fmaxf(v,0.f);
}

// ---------------- CSR SpMM with inline di gather + GCN epilogue ----------------
template<int F>
__global__ void k_spmmf(int n,const int* __restrict__ idx,const float* __restrict__ val,
                        const int* __restrict__ cnt,int maxd,
                        const float* __restrict__ Y,const float* __restrict__ dinv,
                        const float* __restrict__ dfix,const float* __restrict__ b,
                        float* __restrict__ out,int relu){
    int r = blockIdx.x*(256/F) + threadIdx.x/F;
    int c = threadIdx.x%F;
    if(r>=n) return;
    int cn=cnt[r];
    const int* ip=idx+(size_t)r*maxd;
    const float* vp=val+(size_t)r*maxd;
    float acc=0.f;
    for(int e=0;e<cn;e++){
        int s=ip[e];
        acc += vp[e]*dinv[s]*Y[(size_t)s*F+c];
    }
    float fx = dfix? dfix[r] : 2.0f;
    float di = dinv[r];
    float v = di*acc + fx*di*di*Y[(size_t)r*F+c] + b[c];
    out[(size_t)r*F+c] = relu? fmaxf(v,0.f) : v;
}

// CSR SpMM (F=128) + LayerNorm fused
__global__ void __launch_bounds__(256) k_spmmLN(const int* __restrict__ idx,const float* __restrict__ val,
                        const int* __restrict__ cnt,
                        const float* __restrict__ Y,const float* __restrict__ dinv,
                        const float* __restrict__ dfix,const float* __restrict__ b,
                        const float* __restrict__ lg,const float* __restrict__ lb,
                        float* __restrict__ u){
    __shared__ float sh[256];
    int r = blockIdx.x*2 + threadIdx.x/128;
    int c = threadIdx.x%128;
    int base = threadIdx.x & 128;
    int cn=cnt[r];
    const int* ip=idx+(size_t)r*MAXD0;
    const float* vp=val+(size_t)r*MAXD0;
    float acc=0.f;
    for(int e=0;e<cn;e++){
        int s=ip[e];
        acc += vp[e]*dinv[s]*Y[(size_t)s*FO+c];
    }
    float di=dinv[r];
    float v = di*acc + dfix[r]*di*di*Y[(size_t)r*FO+c] + b[c];
    sh[threadIdx.x]=v; __syncthreads();
    for(int o=64;o;o>>=1){ if(c<o) sh[base+c]+=sh[base+c+o]; __syncthreads(); }
    float mu=sh[base]/128.f; __syncthreads();
    float d=v-mu;
    sh[threadIdx.x]=d*d; __syncthreads();
    for(int o=64;o;o>>=1){ if(c<o) sh[base+c]+=sh[base+c+o]; __syncthreads(); }
    float var=sh[base]/128.f;
    u[(size_t)r*FO+c]=d*rsqrtf(var+1e-6f)*lg[c]+lb[c];
}

// ---------------- fused pool: score + CUB block radix topk + ipos + gather ----------------
// key = (monotone_u32(tanh score) << 12) | (4095 - r); descending sort over bits [0,44)
// gives score-descending with index-ascending tie order (matches jax.lax.top_k).
template<int N>
__global__ void __launch_bounds__(1024) k_pool(const float* __restrict__ x,const float* __restrict__ p,
                                               int k,int* __restrict__ perm,float* __restrict__ vals,
                                               int* __restrict__ ipos,float* __restrict__ h){
    constexpr int IT=N/1024;
    typedef cub::BlockRadixSort<unsigned long long,1024,IT> BRS;
    __shared__ typename BRS::TempStorage ts;
    int t=threadIdx.x;
    float pn=0.f;
    #pragma unroll
    for(int c=0;c<FH;c++){ float pv=p[c]; pn+=pv*pv; }
    float rn=rsqrtf(pn);
    unsigned long long keys[IT];
    #pragma unroll
    for(int j=0;j<IT;j++){
        int r=t*IT+j;
        float d=0.f;
        #pragma unroll
        for(int c=0;c<FH;c++) d+=x[(size_t)r*FH+c]*p[c];
        float key=tanhf(d*rn);
        unsigned int f=__float_as_uint(key);
        unsigned int u=f ^ ((f&0x80000000u)? 0xFFFFFFFFu : 0x80000000u);
        keys[j]=((unsigned long long)u<<12) | (unsigned int)(4095-r);
    }
    BRS(ts).SortDescending(keys,0,44);
    #pragma unroll
    for(int j=0;j<IT;j++){
        int pos=t*IT+j;
        int r=4095-(int)(keys[j]&0xFFFu);
        ipos[r]=(pos<k)? pos : -1;
        if(pos<k){
            unsigned int u=(unsigned int)(keys[j]>>12);
            unsigned int f=u ^ ((u&0x80000000u)? 0x80000000u : 0xFFFFFFFFu);
            float key=__uint_as_float(f);
            perm[pos]=r; vals[pos]=key;
            const float4* xr=(const float4*)(x+(size_t)r*FH);
            float4* hr=(float4*)(h+(size_t)pos*FH);
            #pragma unroll
            for(int q=0;q<FH/4;q++){
                float4 v=xr[q];
                v.x*=key; v.y*=key; v.z*=key; v.w*=key;
                hr[q]=v;
            }
        }
    }
}

// ---------------- SpGEMM level1 (CSR out, input HAS diag entries) ----------------
template<int NCOL>
__global__ void __launch_bounds__(256) k_spgemm_csr(
        const int* __restrict__ inIdx,const float* __restrict__ inVal,const int* __restrict__ inCnt,int inMaxd,
        const int* __restrict__ perm,const int* __restrict__ ipos,
        int* __restrict__ outIdx,float* __restrict__ outVal,int* __restrict__ outCnt,int outMaxd,
        float* __restrict__ dinv){
    __shared__ float acc[NCOL];
    int i=blockIdx.x, t=threadIdx.x;
    for(int j=t;j<NCOL;j+=256) acc[j]=0.f;
    __syncthreads();
    int r0=perm[i];
    int cr=inCnt[r0];
    const int* rip=inIdx+(size_t)r0*inMaxd;
    const float* rvp=inVal+(size_t)r0*inMaxd;
    int warp=t>>5, lane=t&31;
    for(int e=warp;e<cr;e+=8){
        int k=rip[e];
        float rv=rvp[e] + ((k==r0)?1.f:0.f);
        int ck=inCnt[k];
        const int* kip=inIdx+(size_t)k*inMaxd;
        const float* kvp=inVal+(size_t)k*inMaxd;
        for(int f=lane;f<ck;f+=32){
            int s=kip[f];
            float cv=kvp[f] + ((s==k)?1.f:0.f);
            int j=ipos[s];
            if(j>=0) atomicAdd(&acc[j], rv*cv);
        }
    }
    __syncthreads();
    if(t==0) acc[i]=0.f;
    __syncthreads();
    if(warp==0){
        int c=0; float rs=0.f;
        for(int base=0;base<NCOL;base+=32){
            int j=base+lane;
            float v=acc[j];
            bool p=(v!=0.f);
            unsigned m=__ballot_sync(0xffffffffu,p);
            if(p){
                int off=c+__popc(m&((1u<<lane)-1u));
                outIdx[(size_t)i*outMaxd+off]=j;
                outVal[(size_t)i*outMaxd+off]=v;
                rs+=v;
            }
            c+=__popc(m);
        }
        #pragma unroll
        for(int o=16;o;o>>=1) rs+=__shfl_xor_sync(0xffffffffu,rs,o);
        if(lane==0){ outCnt[i]=c; dinv[i]=rsqrtf(rs+2.f); }
    }
}

// ---------------- SpGEMM level2 (dense out, input CSR has NO diag) ----------------
template<int NCOL>
__global__ void __launch_bounds__(256) k_spgemm_dense(
        const int* __restrict__ inIdx,const float* __restrict__ inVal,const int* __restrict__ inCnt,int inMaxd,
        const int* __restrict__ perm,const int* __restrict__ ipos,
        float* __restrict__ outD,float* __restrict__ dinv){
    __shared__ float acc[NCOL];
    __shared__ float red[8];
    int i=blockIdx.x, t=threadIdx.x;
    for(int j=t;j<NCOL;j+=256) acc[j]=0.f;
    __syncthreads();
    int r0=perm[i];
    int cr=inCnt[r0];
    int total=cr+1;
    const int* rip=inIdx+(size_t)r0*inMaxd;
    const float* rvp=inVal+(size_t)r0*inMaxd;
    int warp=t>>5, lane=t&31;
    for(int e=warp;e<total;e+=8){
        int k; float rv;
        if(e<cr){ k=rip[e]; rv=rvp[e]; }
        else    { k=r0; rv=1.f; }
        int ck=inCnt[k];
        const int* kip=inIdx+(size_t)k*inMaxd;
        const float* kvp=inVal+(size_t)k*inMaxd;
        int tot2=ck+1;
        for(int f=lane;f<tot2;f+=32){
            int s; float cv;
            if(f<ck){ s=kip[f]; cv=kvp[f]; }
            else    { s=k; cv=1.f; }
            int j=ipos[s];
            if(j>=0) atomicAdd(&acc[j], rv*cv);
        }
    }
    __syncthreads();
    if(t==0) acc[i]=0.f;
    __syncthreads();
    float rs=0.f;
    for(int j=t;j<NCOL;j+=256){ rs+=acc[j]; outD[(size_t)i*NCOL+j]=acc[j]; }
    #pragma unroll
    for(int o=16;o;o>>=1) rs+=__shfl_xor_sync(0xffffffffu,rs,o);
    if(lane==0) red[warp]=rs;
    __syncthreads();
    if(t==0){
        float s=0.f;
        #pragma unroll
        for(int w=0;w<8;w++) s+=red[w];
        dinv[i]=rsqrtf(s+2.f);
    }
}

// ---------------- level-3 gathers ----------------
__global__ void k_gatherR(const float* __restrict__ A,int n,const int* __restrict__ perm,int m,float* __restrict__ R){
    size_t t=(size_t)blockIdx.x*blockDim.x+threadIdx.x;
    if(t>=(size_t)m*n) return;
    int i=(int)(t/n), k=(int)(t%n);
    int pi=perm[i];
    R[t]=A[(size_t)pi*n+k] + ((k==pi)?1.f:0.f);
}
__global__ void k_gatherC(const float* __restrict__ A,int n,const int* __restrict__ perm,int m,float* __restrict__ C){
    size_t t=(size_t)blockIdx.x*blockDim.x+threadIdx.x;
    if(t>=(size_t)m*n) return;
    int k=(int)(t/m), j=(int)(t%m);
    int pj=perm[j];
    C[t]=A[(size_t)k*n+pj] + ((k==pj)?1.f:0.f);
}

// ---------------- GAT ----------------
__global__ void k_esed(const float* __restrict__ feat,const float* __restrict__ asrc,const float* __restrict__ adst,int heads,float* __restrict__ es,float* __restrict__ ed){
    int w=(blockIdx.x*blockDim.x+threadIdx.x)>>5;
    int lane=threadIdx.x&31;
    if(w>=N0) return;
    for(int h=0;h<heads;h++){
        float a=0.f,d=0.f;
        for(int c=lane;c<FO;c+=32){
            float f=feat[(size_t)w*(heads*FO)+h*FO+c];
            a+=f*asrc[h*FO+c];
            d+=f*adst[h*FO+c];
        }
        #pragma unroll
        for(int o=16;o;o>>=1){ a+=__shfl_xor_sync(0xffffffffu,a,o); d+=__shfl_xor_sync(0xffffffffu,d,o); }
        if(lane==0){ es[w*heads+h]=a; ed[w*heads+h]=d; }
    }
}

template<int HEADS,int MODE>
__global__ void __launch_bounds__(128) k_gat(const float* __restrict__ feat,const float* __restrict__ es,const float* __restrict__ ed,
                                             const float* __restrict__ bias,const float* __restrict__ res,const float* __restrict__ resb,
                                             float* __restrict__ out){
    __shared__ int snbr[MAXD0];
    __shared__ float salpha[MAXD0*HEADS];
    __shared__ float smax[HEADS], sinv[HEADS];
    int d=blockIdx.x, t=threadIdx.x;
    int cnt=g_cnt0[d];
    for(int i=t;i<cnt;i+=128) snbr[i]=g_idx0[(size_t)d*MAXD0+i];
    __syncthreads();
    for(int i=t;i<cnt;i+=128){
        int s=snbr[i];
        #pragma unroll
        for(int h=0;h<HEADS;h++){
            float l=ed[d*HEADS+h]+es[s*HEADS+h];
            l = (l>0.f)? l : 0.2f*l;
            salpha[i*HEADS+h]=l;
        }
    }
    __syncthreads();
    if(t<HEADS){
        float mx=-1e30f;
        for(int i=0;i<cnt;i++) mx=fmaxf(mx,salpha[i*HEADS+t]);
        float sm=0.f;
        for(int i=0;i<cnt;i++) sm+=expf(salpha[i*HEADS+t]-mx);
        smax[t]=mx; sinv[t]=1.f/sm;
    }
    __syncthreads();
    for(int i=t;i<cnt*HEADS;i+=128){
        int h=i%HEADS;
        salpha[i]=expf(salpha[i]-smax[h])*sinv[h];
    }
    __syncthreads();
    #pragma unroll
    for(int h=0;h<HEADS;h++){
        float acc=0.f;
        for(int i=0;i<cnt;i++)
            acc += salpha[i*HEADS+h]*feat[(size_t)snbr[i]*(HEADS*FO)+h*FO+t];
        if(MODE==0){
            float v=acc+bias[h*FO+t];
            out[(size_t)d*(HEADS*FO)+h*FO+t]= (v>0.f)? v : expm1f(v);
        } else {
            out[(size_t)d*FO+t]=acc+bias[t]+res[(size_t)d*FO+t]+resb[t];
        }
    }
}

// ---------------- host ----------------
template<typename T> static T* symaddr(const void* sym){
    void* p=nullptr;
    cudaGetSymbolAddress(&p, sym);
    return (T*)p;
}

static void gBig(int M,int N,int K,int KS,const float*A,const float*B,float*dest,
                 const float*bs,cudaStream_t st){
    dim3 g(N/64, M/64, KS);
    if(bs) gemmBig<1><<<g,256,0,st>>>(M,N,K,KS,A,B,dest,bs);
    else   gemmBig<0><<<g,256,0,st>>>(M,N,K,KS,A,B,dest,nullptr);
}
static void g16(int M,int N,int K,const float*A,const float*B,float*C,cudaStream_t st){
    dim3 g(N/64, M/16);
    gemm16<0><<<g,256,0,st>>>(M,N,K,A,B,C,nullptr,nullptr);
}
static void g16_m(int M,int N,int K,const float*A,const float*B,float*C,const int*ipos,const float*xs){
    dim3 g(N/64, M/16);
    gemm16<1><<<g,256>>>(M,N,K,A,B,C,ipos,xs);
}

extern "C" void kernel_launch(void* const* d_in, const int* in_sizes, int n_in,
                              void* d_out, int out_size) {
    const float* x      =(const float*)d_in[0];
    const int*   ei     =(const int*  )d_in[1];
    const float* w0=(const float*)d_in[2],  *b0=(const float*)d_in[3];
    const float* w1=(const float*)d_in[4],  *b1=(const float*)d_in[5];
    const float* w2=(const float*)d_in[6],  *b2=(const float*)d_in[7];
    const float* w3=(const float*)d_in[8],  *b3=(const float*)d_in[9];
    const float* p1=(const float*)d_in[10], *p2=(const float*)d_in[11], *p3=(const float*)d_in[12];
    const float* uw0=(const float*)d_in[13],*ub0=(const float*)d_in[14];
    const float* uw1=(const float*)d_in[15],*ub1=(const float*)d_in[16];
    const float* uw2=(const float*)d_in[17],*ub2=(const float*)d_in[18];
    const float* lng=(const float*)d_in[19],*lnb=(const float*)d_in[20];
    const float* resw=(const float*)d_in[21],*resb=(const float*)d_in[22];
    const float* g1w=(const float*)d_in[23],*g1as=(const float*)d_in[24],*g1ad=(const float*)d_in[25],*g1b=(const float*)d_in[26];
    const float* g2w=(const float*)d_in[27],*g2as=(const float*)d_in[28],*g2ad=(const float*)d_in[29],*g2b=(const float*)d_in[30];

    unsigned char* A0b=symaddr<unsigned char>(g_A0b);
    int* idx0=symaddr<int>(g_idx0); float* val0=symaddr<float>(g_val0); int* cnt0=symaddr<int>(g_cnt0);
    int* idx1=symaddr<int>(g_idx1); float* val1=symaddr<float>(g_val1); int* cnt1=symaddr<int>(g_cnt1);
    float* A2d=symaddr<float>(g_A2d); float* A3d=symaddr<float>(g_A3d);
    float* Rg=symaddr<float>(g_Rg); float* Cg=symaddr<float>(g_Cg);
    float* part=symaddr<float>(g_part);
    float* Y=symaddr<float>(g_Y);   float* S=symaddr<float>(g_S);
    float* x0b=symaddr<float>(g_x0);float* x1b=symaddr<float>(g_x1);
    float* x2b=symaddr<float>(g_x2);float* x3b=symaddr<float>(g_x3);
    float* hb=symaddr<float>(g_hbuf); float* upb=symaddr<float>(g_up);
    float* Ub=symaddr<float>(g_U);  float* Rb=symaddr<float>(g_res);
    float* F1=symaddr<float>(g_feat1); float* GO=symaddr<float>(g_gout);
    float* di0=symaddr<float>(g_dinv0); float* df0=symaddr<float>(g_dfix0);
    float* di1=symaddr<float>(g_dinv1); float* di2=symaddr<float>(g_dinv2); float* di3=symaddr<float>(g_dinv3);
    int* pm1=symaddr<int>(g_perm1); float* vl1=symaddr<float>(g_vals1);
    int* pm2=symaddr<int>(g_perm2); float* vl2=symaddr<float>(g_vals2);
    int* pm3=symaddr<int>(g_perm3); float* vl3=symaddr<float>(g_vals3);
    int* ip1=symaddr<int>(g_ipos1); int* ip2=symaddr<int>(g_ipos2); int* ip3=symaddr<int>(g_ipos3);
    float* ES=symaddr<float>(g_es); float* ED=symaddr<float>(g_ed);
    float* out=(float*)d_out;

    // side stream + events
    static cudaStream_t s2=nullptr;
    static cudaEvent_t ev[8];
    if(!s2){
        cudaStreamCreateWithFlags(&s2,cudaStreamNonBlocking);
        for(int i=0;i<8;i++) cudaEventCreateWithFlags(&ev[i],cudaEventDisableTiming);
    }
    auto FORK=[&](int i){ cudaEventRecord(ev[i],0); cudaStreamWaitEvent(s2,ev[i],0); };
    auto JOIN=[&](int i){ cudaEventRecord(ev[4+i],s2); cudaStreamWaitEvent(0,ev[4+i],0); };

    // ---- build A0 (bytes) + CSR0 ----
    cudaMemsetAsync(A0b,0,(size_t)N0*N0,0);
    k_buildA0<<<cdiv(NE,256),256>>>(ei,(unsigned int*)A0b);
    k_csr0<<<cdiv(N0,8),256>>>(A0b,idx0,val0,cnt0,di0,df0);

    // ---- gcn0 down (x@w0 fused into SpMM) ----
    k_spmm0<<<N0/4,256>>>(idx0,val0,cnt0,di0,df0,x,w0,b0,x0b);

    // ---- pool1 ; [SpGEMM1 || feature GEMM1] ----
    k_pool<N0><<<1,1024>>>(x0b,p1,N1,pm1,vl1,ip1,hb);
    FORK(0);
    k_spgemm_csr<N1><<<N1,256,0,s2>>>(idx0,val0,cnt0,MAXD0,pm1,ip1,idx1,val1,cnt1,MAXD1,di1);
    g16(N1,FH,FH,hb,w1,Y,0);
    JOIN(0);
    k_spmmf<64><<<cdiv(N1*64,256),256>>>(N1,idx1,val1,cnt1,MAXD1,Y,di1,nullptr,b1,x1b,1);

    // ---- pool2 ; [SpGEMM2(dense) || feature GEMM2] ----
    k_pool<N1><<<1,1024>>>(x1b,p2,N2,pm2,vl2,ip2,hb);
    FORK(1);
    k_spgemm_dense<N2><<<N2,256,0,s2>>>(idx1,val1,cnt1,MAXD1,pm2,ip2,A2d,di2);
    g16(N2,FH,FH,hb,w2,Y,0);
    JOIN(1);
    gBig(N2,FH,N2,8,A2d,Y,part,di2,0);
    k_kred_gcn<<<cdiv(N2*FH,256),256>>>(N2,FH,8,part,Y,di2,b2,x2b,1);

    // ---- pool3 ; [A3 construction || feature GEMM3] ----
    k_pool<N2><<<1,1024>>>(x2b,p3,N3,pm3,vl3,ip3,hb);
    FORK(2);
    k_gatherR<<<cdiv(N3*N2,256),256,0,s2>>>(A2d,N2,pm3,N3,Rg);
    k_gatherC<<<cdiv(N3*N2,256),256,0,s2>>>(A2d,N2,pm3,N3,Cg);
    gBig(N3,N3,N2,4,Rg,Cg,part,nullptr,s2);
    k_finishA3red<<<N3,256,0,s2>>>(part,A3d,di3);
    g16(N3,FH,FH,hb,w3,Y,0);
    JOIN(2);
    gBig(N3,FH,N3,8,A3d,Y,part,di3,0);
    k_kred_gcn<<<cdiv(N3*FH,256),256>>>(N3,FH,8,part,Y,di3,b3,x3b,1);

    // ---- up path ----
    g16_m(N2,FH,FH,x2b,uw0,Y,ip3,x3b);
    gBig(N2,FH,N2,8,A2d,Y,part,di2,0);
    k_kred_gcn<<<cdiv(N2*FH,256),256>>>(N2,FH,8,part,Y,di2,ub0,upb,1);

    g16_m(N1,FH,FH,x1b,uw1,Y,ip2,upb);
    k_spmmf<64><<<cdiv(N1*64,256),256>>>(N1,idx1,val1,cnt1,MAXD1,Y,di1,nullptr,ub1,upb,1);

    g16_m(N0,FO,FH,x0b,uw2,Y,ip1,upb);
    k_spmmLN<<<N0/2,256>>>(idx0,val0,cnt0,Y,di0,df0,ub2,lng,lnb,Ub);

    // ---- [residual GEMM || GAT1 chain] ----
    FORK(3);
    gBig(N0,FO,FO,1,Ub,resw,Rb,nullptr,s2);
    gBig(N0,4*FO,FO,1,Ub,g1w,F1,nullptr,0);
    k_esed<<<cdiv(N0,8),256>>>(F1,g1as,g1ad,4,ES,ED);
    k_gat<4,0><<<N0,128>>>(F1,ES,ED,g1b,nullptr,nullptr,GO);
    gBig(N0,FO,4*FO,1,GO,g2w,S,nullptr,0);
    k_esed<<<cdiv(N0,8),256>>>(S,g2as,g2ad,1,ES,ED);
    JOIN(3);
    k_gat<1,1><<<N0,128>>>(S,ES,ED,g2b,Rb,resb,out);
}

// round 14
// speedup vs baseline: 1.5798x; 1.5798x over previous
#include <cuda_runtime.h>
#include <cuda_bf16.h>
#include <math.h>

// ---------------- problem constants ----------------
#define N0 4096
#define N1 2048
#define N2 1024
#define N3 512
#define NE 65536
#define FH 64
#define FO 128
#define MAXD0 128
#define MAXD1 2048

// ---------------- static device scratch ----------------
__device__ unsigned char g_A0b[(size_t)N0*N0];
__device__ int   g_idx0[(size_t)N0*MAXD0]; __device__ float g_val0[(size_t)N0*MAXD0]; __device__ int g_cnt0[N0];
__device__ int   g_idx1[(size_t)N1*MAXD1]; __device__ float g_val1[(size_t)N1*MAXD1]; __device__ int g_cnt1[N1];
__device__ float g_A2d[(size_t)N2*N2];
__device__ float g_A3d[(size_t)N3*N3];
__device__ float g_Rg[(size_t)N3*N2];
__device__ float g_Cg[(size_t)N2*N3];
__device__ float g_part[1<<20];
__device__ float g_Y[(size_t)N0*FO];
__device__ float g_S[(size_t)N0*FO];
__device__ float g_x0[N0*FH], g_x1[N1*FH], g_x2[N2*FH], g_x3[N3*FH];
__device__ float g_hbuf[N0*FH];
__device__ float g_up[N1*FH];
__device__ float g_U[N0*FO];
__device__ float g_res[N0*FO];
__device__ float g_feat1[(size_t)N0*512];
__device__ float g_gout[(size_t)N0*512];
__device__ float g_dinv0[N0], g_dfix0[N0];
__device__ float g_dinv1[N1], g_dinv2[N2], g_dinv3[N3];
__device__ unsigned long long g_keys[N0];
__device__ int   g_perm1[N1]; __device__ float g_vals1[N1];
__device__ int   g_perm2[N2]; __device__ float g_vals2[N2];
__device__ int   g_perm3[N3]; __device__ float g_vals3[N3];
__device__ int   g_ipos1[N0], g_ipos2[N1], g_ipos3[N2];
__device__ float g_es[N0*4], g_ed[N0*4];

static inline int cdiv(int a,int b){return (a+b-1)/b;}

// ---------------- gemmBig: 64x64x16, TM=TN=4, optional split-K, optional B row-scale ----------------
template<int BSCALE>
__global__ void __launch_bounds__(256)
gemmBig(int M,int N,int K,int KS,const float* __restrict__ A,const float* __restrict__ B,
        float* __restrict__ dest,const float* __restrict__ bs){
    __shared__ __align__(16) float As[16][64];
    __shared__ __align__(16) float Bs[16][64];
    const int bm=blockIdx.y*64, bn=blockIdx.x*64, z=blockIdx.z;
    const int tid=threadIdx.x;
    const int trow=tid/16, tcol=tid%16;
    const int kchunk=K/KS;
    const int kbeg=z*kchunk, kend=kbeg+kchunk;
    float acc[4][4];
    #pragma unroll
    for(int i=0;i<4;i++)
        #pragma unroll
        for(int j=0;j<4;j++) acc[i][j]=0.f;

    for(int k0=kbeg;k0<kend;k0+=16){
        {
            int m=tid/4, kq=tid%4;
            float4 v=*(const float4*)(A+(size_t)(bm+m)*K+k0+kq*4);
            As[kq*4+0][m]=v.x; As[kq*4+1][m]=v.y; As[kq*4+2][m]=v.z; As[kq*4+3][m]=v.w;
        }
        {
            int k=tid/16, nq=tid%16;
            float4 v=*(const float4*)(B+(size_t)(k0+k)*N+bn+nq*4);
            if(BSCALE){
                float s=bs[k0+k];
                v.x*=s; v.y*=s; v.z*=s; v.w*=s;
            }
            *(float4*)&Bs[k][nq*4]=v;
        }
        __syncthreads();
        #pragma unroll
        for(int kk=0;kk<16;kk++){
            float4 ra=*(const float4*)&As[kk][trow*4];
            float4 rb=*(const float4*)&Bs[kk][tcol*4];
            float a[4]={ra.x,ra.y,ra.z,ra.w};
            float b[4]={rb.x,rb.y,rb.z,rb.w};
            #pragma unroll
            for(int i=0;i<4;i++)
                #pragma unroll
                for(int j=0;j<4;j++) acc[i][j]+=a[i]*b[j];
        }
        __syncthreads();
    }
    float* out=dest+(size_t)z*M*N;
    #pragma unroll
    for(int i=0;i<4;i++){
        int gm=bm+trow*4+i;
        #pragma unroll
        for(int j=0;j<4;j++){
            out[(size_t)gm*N+bn+tcol*4+j]=acc[i][j];
        }
    }
}

// split-K reduce + GCN epilogue (raw Y): v = di*acc + 2*di*di*Y + b
__global__ void k_kred_gcn(int n,int f,int KS,const float* __restrict__ part,
                           const float* __restrict__ Y,const float* __restrict__ di,
                           const float* __restrict__ b,float* __restrict__ out,int relu){
    int t=blockIdx.x*blockDim.x+threadIdx.x;
    if(t>=n*f) return;
    float acc=0.f;
    for(int z=0;z<KS;z++) acc+=part[(size_t)z*n*f+t];
    int r=t/f;
    float d=di[r];
    float v=d*acc + 2.f*d*d*Y[t] + b[t%f];
    out[t]= relu? fmaxf(v,0.f) : v;
}

// A3 split-K reduce (KS=4) + zero diag + rowsum -> dinv3
__global__ void __launch_bounds__(256) k_finishA3red(const float* __restrict__ part,
                                                     float* __restrict__ A3,float* __restrict__ dinv){
    __shared__ float red[8];
    int r=blockIdx.x, t=threadIdx.x;
    float s=0.f;
    for(int j=t;j<N3;j+=256){
        float acc=part[(size_t)0*N3*N3 + r*N3 + j]
                 +part[(size_t)1*N3*N3 + r*N3 + j]
                 +part[(size_t)2*N3*N3 + r*N3 + j]
                 +part[(size_t)3*N3*N3 + r*N3 + j];
        if(j==r) acc=0.f;
        A3[(size_t)r*N3+j]=acc;
        s+=acc;
    }
    #pragma unroll
    for(int o=16;o;o>>=1) s+=__shfl_xor_sync(0xffffffffu,s,o);
    if((t&31)==0) red[t>>5]=s;
    __syncthreads();
    if(t==0){
        float ss=0.f;
        #pragma unroll
        for(int w=0;w<8;w++) ss+=red[w];
        dinv[r]=rsqrtf(ss+2.f);
    }
}

// ---------------- gemm16: 16x64x16, TM=1,TN=4 ----------------
template<int MERGE>
__global__ void __launch_bounds__(256)
gemm16(int M,int N,int K,const float* __restrict__ Af,const float* __restrict__ B,
       float* __restrict__ C,const int* __restrict__ ipos,const float* __restrict__ xs){
    __shared__ __align__(16) float As[16][16];
    __shared__ __align__(16) float Bs[16][64];
    const int bm=blockIdx.y*16, bn=blockIdx.x*64;
    const int tid=threadIdx.x;
    const int trow=tid/16, tcol=tid%16;
    float acc[4]={0.f,0.f,0.f,0.f};
    for(int k0=0;k0<K;k0+=16){
        {
            int m=tid/16, k=tid%16;
            int gm=bm+m, gk=k0+k;
            float a=Af[(size_t)gm*K+gk];
            if(MERGE){ int j=ipos[gm]; if(j>=0) a+=xs[(size_t)j*K+gk]; }
            As[k][m]=a;
        }
        {
            int k=tid/16, nq=tid%16;
            *(float4*)&Bs[k][nq*4] = *(const float4*)(B+(size_t)(k0+k)*N+bn+nq*4);
        }
        __syncthreads();
        #pragma unroll
        for(int kk=0;kk<16;kk++){
            float a=As[kk][trow];
            float4 rb=*(const float4*)&Bs[kk][tcol*4];
            acc[0]+=a*rb.x; acc[1]+=a*rb.y; acc[2]+=a*rb.z; acc[3]+=a*rb.w;
        }
        __syncthreads();
    }
    int gm=bm+trow;
    #pragma unroll
    for(int j=0;j<4;j++)
        C[(size_t)gm*N+bn+tcol*4+j]=acc[j];
}

// ---------------- graph build ----------------
__global__ void k_buildA0(const int* __restrict__ ei, unsigned int* __restrict__ Aw){
    int e = blockIdx.x*blockDim.x+threadIdx.x;
    if(e<NE){
        int s=ei[e];
        int d=ei[NE+e];
        size_t byteoff=(size_t)d*N0+s;
        atomicAdd(&Aw[byteoff>>2], 1u<<((s&3)*8));
    }
}

__global__ void k_csr0(const unsigned char* __restrict__ Ab,int* __restrict__ idx,float* __restrict__ val,
                       int* __restrict__ cnt,float* __restrict__ dinv,float* __restrict__ dfix){
    int w=(blockIdx.x*blockDim.x+threadIdx.x)>>5;
    int lane=threadIdx.x&31;
    if(w>=N0) return;
    const unsigned int* row=(const unsigned int*)(Ab+(size_t)w*N0);
    int c=0; float rs=0.f;
    for(int base=0;base<N0/4;base+=32){
        unsigned int wv=row[base+lane];
        int colbase=(base+lane)*4;
        #pragma unroll
        for(int b=0;b<4;b++){
            int v=(wv>>(8*b))&255;
            int col=colbase+b;
            bool p=(v!=0)||(col==w);
            unsigned m=__ballot_sync(0xffffffffu,p);
            if(p){
                int off=c+__popc(m&((1u<<lane)-1u));
                idx[(size_t)w*MAXD0+off]=col;
                val[(size_t)w*MAXD0+off]=(float)v;
                rs+=(float)v;
            }
            c+=__popc(m);
        }
    }
    #pragma unroll
    for(int o=16;o;o>>=1) rs+=__shfl_xor_sync(0xffffffffu,rs,o);
    if(lane==0){
        float d=(float)Ab[(size_t)w*N0+w];
        float fx=(d==0.f)?2.f:0.f;
        cnt[w]=c;
        dfix[w]=fx;
        dinv[w]=rsqrtf(rs+fx);
    }
}

// ---------------- level0 fused SpMM ----------------
__global__ void __launch_bounds__(256) k_spmm0(const int* __restrict__ idx,const float* __restrict__ val,
                        const int* __restrict__ cnt,const float* __restrict__ dinv,
                        const float* __restrict__ dfix,
                        const float* __restrict__ x,const float* __restrict__ w,
                        const float* __restrict__ b,float* __restrict__ out){
    __shared__ float sw[3*FH];
    if(threadIdx.x<3*FH) sw[threadIdx.x]=w[threadIdx.x];
    __syncthreads();
    int r = blockIdx.x*4 + threadIdx.x/FH;
    int c = threadIdx.x%FH;
    int cn=cnt[r];
    const int* ip=idx+(size_t)r*MAXD0;
    const float* vp=val+(size_t)r*MAXD0;
    float w0c=sw[c], w1c=sw[FH+c], w2c=sw[2*FH+c];
    float acc=0.f;
    for(int e=0;e<cn;e++){
        int s=ip[e];
        const float* xr=x+(size_t)s*3;
        float ys=dinv[s]*(xr[0]*w0c+xr[1]*w1c+xr[2]*w2c);
        acc += vp[e]*ys;
    }
    float di=dinv[r];
    const float* xr=x+(size_t)r*3;
    float ysS=di*(xr[0]*w0c+xr[1]*w1c+xr[2]*w2c);
    float v = di*acc + dfix[r]*di*ysS + b[c];
    out[(size_t)r*FH+c]=fmaxf(v,0.f);
}

// ---------------- CSR SpMM with inline di gather + GCN epilogue ----------------
template<int F>
__global__ void k_spmmf(int n,const int* __restrict__ idx,const float* __restrict__ val,
                        const int* __restrict__ cnt,int maxd,
                        const float* __restrict__ Y,const float* __restrict__ dinv,
                        const float* __restrict__ dfix,const float* __restrict__ b,
                        float* __restrict__ out,int relu){
    int r = blockIdx.x*(256/F) + threadIdx.x/F;
    int c = threadIdx.x%F;
    if(r>=n) return;
    int cn=cnt[r];
    const int* ip=idx+(size_t)r*maxd;
    const float* vp=val+(size_t)r*maxd;
    float acc=0.f;
    for(int e=0;e<cn;e++){
        int s=ip[e];
        acc += vp[e]*dinv[s]*Y[(size_t)s*F+c];
    }
    float fx = dfix? dfix[r] : 2.0f;
    float di = dinv[r];
    float v = di*acc + fx*di*di*Y[(size_t)r*F+c] + b[c];
    out[(size_t)r*F+c] = relu? fmaxf(v,0.f) : v;
}

// CSR SpMM (F=128) + LayerNorm fused
__global__ void __launch_bounds__(256) k_spmmLN(const int* __restrict__ idx,const float* __restrict__ val,
                        const int* __restrict__ cnt,
                        const float* __restrict__ Y,const float* __restrict__ dinv,
                        const float* __restrict__ dfix,const float* __restrict__ b,
                        const float* __restrict__ lg,const float* __restrict__ lb,
                        float* __restrict__ u){
    __shared__ float sh[256];
    int r = blockIdx.x*2 + threadIdx.x/128;
    int c = threadIdx.x%128;
    int base = threadIdx.x & 128;
    int cn=cnt[r];
    const int* ip=idx+(size_t)r*MAXD0;
    const float* vp=val+(size_t)r*MAXD0;
    float acc=0.f;
    for(int e=0;e<cn;e++){
        int s=ip[e];
        acc += vp[e]*dinv[s]*Y[(size_t)s*FO+c];
    }
    float di=dinv[r];
    float v = di*acc + dfix[r]*di*di*Y[(size_t)r*FO+c] + b[c];
    sh[threadIdx.x]=v; __syncthreads();
    for(int o=64;o;o>>=1){ if(c<o) sh[base+c]+=sh[base+c+o]; __syncthreads(); }
    float mu=sh[base]/128.f; __syncthreads();
    float d=v-mu;
    sh[threadIdx.x]=d*d; __syncthreads();
    for(int o=64;o;o>>=1){ if(c<o) sh[base+c]+=sh[base+c+o]; __syncthreads(); }
    float var=sh[base]/128.f;
    u[(size_t)r*FO+c]=d*rsqrtf(var+1e-6f)*lg[c]+lb[c];
}

// ---------------- pool via brute-force exact rank (multi-SM) ----------------
// key = (monotone_u32(tanh score) << 12) | (4095 - r): all keys distinct, so
// rank(r) = #{keys > key_r} is exactly the position jax.lax.top_k would assign
// (score desc, ties index asc). Two small kernels replace the single-SM sort.
__global__ void k_scorek(int n,const float* __restrict__ x,const float* __restrict__ p,
                         unsigned long long* __restrict__ keys){
    int w=(blockIdx.x*blockDim.x+threadIdx.x)>>5;
    int lane=threadIdx.x&31;
    if(w>=n) return;
    float pn=0.f,d=0.f;
    #pragma unroll
    for(int c=lane;c<FH;c+=32){ float pv=p[c]; pn+=pv*pv; d+=x[(size_t)w*FH+c]*pv; }
    #pragma unroll
    for(int o=16;o;o>>=1){ d+=__shfl_xor_sync(0xffffffffu,d,o); pn+=__shfl_xor_sync(0xffffffffu,pn,o); }
    if(lane==0){
        float key=tanhf(d*rsqrtf(pn));
        unsigned int f=__float_as_uint(key);
        unsigned int u=f ^ ((f&0x80000000u)? 0xFFFFFFFFu : 0x80000000u);
        keys[w]=((unsigned long long)u<<12) | (unsigned int)(4095-w);
    }
}

template<int N>
__global__ void __launch_bounds__(256) k_rank(const unsigned long long* __restrict__ keys,int k,
                        const float* __restrict__ x,int* __restrict__ perm,float* __restrict__ vals,
                        int* __restrict__ ipos,float* __restrict__ h){
    __shared__ unsigned long long sk[N];
    int t=threadIdx.x;
    for(int i=t;i<N;i+=256) sk[i]=keys[i];
    __syncthreads();
    int r=blockIdx.x*256+t;
    unsigned long long my=sk[r];
    int rank=0;
    #pragma unroll 8
    for(int j=0;j<N;j++) rank += (sk[j]>my);
    if(rank<k){
        unsigned int u=(unsigned int)(my>>12);
        unsigned int f=u ^ ((u&0x80000000u)? 0x80000000u : 0xFFFFFFFFu);
        float key=__uint_as_float(f);
        perm[rank]=r; vals[rank]=key; ipos[r]=rank;
        const float4* xr=(const float4*)(x+(size_t)r*FH);
        float4* hr=(float4*)(h+(size_t)rank*FH);
        #pragma unroll
        for(int q=0;q<FH/4;q++){
            float4 v=xr[q];
            v.x*=key; v.y*=key; v.z*=key; v.w*=key;
            hr[q]=v;
        }
    } else {
        ipos[r]=-1;
    }
}

// ---------------- SpGEMM level1 (CSR out, input HAS diag entries) ----------------
template<int NCOL>
__global__ void __launch_bounds__(256) k_spgemm_csr(
        const int* __restrict__ inIdx,const float* __restrict__ inVal,const int* __restrict__ inCnt,int inMaxd,
        const int* __restrict__ perm,const int* __restrict__ ipos,
        int* __restrict__ outIdx,float* __restrict__ outVal,int* __restrict__ outCnt,int outMaxd,
        float* __restrict__ dinv){
    __shared__ float acc[NCOL];
    int i=blockIdx.x, t=threadIdx.x;
    for(int j=t;j<NCOL;j+=256) acc[j]=0.f;
    __syncthreads();
    int r0=perm[i];
    int cr=inCnt[r0];
    const int* rip=inIdx+(size_t)r0*inMaxd;
    const float* rvp=inVal+(size_t)r0*inMaxd;
    int warp=t>>5, lane=t&31;
    for(int e=warp;e<cr;e+=8){
        int k=rip[e];
        float rv=rvp[e] + ((k==r0)?1.f:0.f);
        int ck=inCnt[k];
        const int* kip=inIdx+(size_t)k*inMaxd;
        const float* kvp=inVal+(size_t)k*inMaxd;
        for(int f=lane;f<ck;f+=32){
            int s=kip[f];
            float cv=kvp[f] + ((s==k)?1.f:0.f);
            int j=ipos[s];
            if(j>=0) atomicAdd(&acc[j], rv*cv);
        }
    }
    __syncthreads();
    if(t==0) acc[i]=0.f;
    __syncthreads();
    if(warp==0){
        int c=0; float rs=0.f;
        for(int base=0;base<NCOL;base+=32){
            int j=base+lane;
            float v=acc[j];
            bool p=(v!=0.f);
            unsigned m=__ballot_sync(0xffffffffu,p);
            if(p){
                int off=c+__popc(m&((1u<<lane)-1u));
                outIdx[(size_t)i*outMaxd+off]=j;
                outVal[(size_t)i*outMaxd+off]=v;
                rs+=v;
            }
            c+=__popc(m);
        }
        #pragma unroll
        for(int o=16;o;o>>=1) rs+=__shfl_xor_sync(0xffffffffu,rs,o);
        if(lane==0){ outCnt[i]=c; dinv[i]=rsqrtf(rs+2.f); }
    }
}

// ---------------- SpGEMM level2 (dense out, input CSR has NO diag) ----------------
template<int NCOL>
__global__ void __launch_bounds__(256) k_spgemm_dense(
        const int* __restrict__ inIdx,const float* __restrict__ inVal,const int* __restrict__ inCnt,int inMaxd,
        const int* __restrict__ perm,const int* __restrict__ ipos,
        float* __restrict__ outD,float* __restrict__ dinv){
    __shared__ float acc[NCOL];
    __shared__ float red[8];
    int i=blockIdx.x, t=threadIdx.x;
    for(int j=t;j<NCOL;j+=256) acc[j]=0.f;
    __syncthreads();
    int r0=perm[i];
    int cr=inCnt[r0];
    int total=cr+1;
    const int* rip=inIdx+(size_t)r0*inMaxd;
    const float* rvp=inVal+(size_t)r0*inMaxd;
    int warp=t>>5, lane=t&31;
    for(int e=warp;e<total;e+=8){
        int k; float rv;
        if(e<cr){ k=rip[e]; rv=rvp[e]; }
        else    { k=r0; rv=1.f; }
        int ck=inCnt[k];
        const int* kip=inIdx+(size_t)k*inMaxd;
        const float* kvp=inVal+(size_t)k*inMaxd;
        int tot2=ck+1;
        for(int f=lane;f<tot2;f+=32){
            int s; float cv;
            if(f<ck){ s=kip[f]; cv=kvp[f]; }
            else    { s=k; cv=1.f; }
            int j=ipos[s];
            if(j>=0) atomicAdd(&acc[j], rv*cv);
        }
    }
    __syncthreads();
    if(t==0) acc[i]=0.f;
    __syncthreads();
    float rs=0.f;
    for(int j=t;j<NCOL;j+=256){ rs+=acc[j]; outD[(size_t)i*NCOL+j]=acc[j]; }
    #pragma unroll
    for(int o=16;o;o>>=1) rs+=__shfl_xor_sync(0xffffffffu,rs,o);
    if(lane==0) red[warp]=rs;
    __syncthreads();
    if(t==0){
        float s=0.f;
        #pragma unroll
        for(int w=0;w<8;w++) s+=red[w];
        dinv[i]=rsqrtf(s+2.f);
    }
}

// ---------------- level-3 gathers ----------------
__global__ void k_gatherR(const float* __restrict__ A,int n,const int* __restrict__ perm,int m,float* __restrict__ R){
    size_t t=(size_t)blockIdx.x*blockDim.x+threadIdx.x;
    if(t>=(size_t)m*n) return;
    int i=(int)(t/n), k=(int)(t%n);
    int pi=perm[i];
    R[t]=A[(size_t)pi*n+k] + ((k==pi)?1.f:0.f);
}
__global__ void k_gatherC(const float* __restrict__ A,int n,const int* __restrict__ perm,int m,float* __restrict__ C){
    size_t t=(size_t)blockIdx.x*blockDim.x+threadIdx.x;
    if(t>=(size_t)m*n) return;
    int k=(int)(t/m), j=(int)(t%m);
    int pj=perm[j];
    C[t]=A[(size_t)k*n+pj] + ((k==pj)?1.f:0.f);
}

// ---------------- GAT ----------------
__global__ void k_esed(const float* __restrict__ feat,const float* __restrict__ asrc,const float* __restrict__ adst,int heads,float* __restrict__ es,float* __restrict__ ed){
    int w=(blockIdx.x*blockDim.x+threadIdx.x)>>5;
    int lane=threadIdx.x&31;
    if(w>=N0) return;
    for(int h=0;h<heads;h++){
        float a=0.f,d=0.f;
        for(int c=lane;c<FO;c+=32){
            float f=feat[(size_t)w*(heads*FO)+h*FO+c];
            a+=f*asrc[h*FO+c];
            d+=f*adst[h*FO+c];
        }
        #pragma unroll
        for(int o=16;o;o>>=1){ a+=__shfl_xor_sync(0xffffffffu,a,o); d+=__shfl_xor_sync(0xffffffffu,d,o); }
        if(lane==0){ es[w*heads+h]=a; ed[w*heads+h]=d; }
    }
}

template<int HEADS,int MODE>
__global__ void __launch_bounds__(128) k_gat(const float* __restrict__ feat,const float* __restrict__ es,const float* __restrict__ ed,
                                             const float* __restrict__ bias,const float* __restrict__ res,const float* __restrict__ resb,
                                             float* __restrict__ out){
    __shared__ int snbr[MAXD0];
    __shared__ float salpha[MAXD0*HEADS];
    __shared__ float smax[HEADS], sinv[HEADS];
    int d=blockIdx.x, t=threadIdx.x;
    int cnt=g_cnt0[d];
    for(int i=t;i<cnt;i+=128) snbr[i]=g_idx0[(size_t)d*MAXD0+i];
    __syncthreads();
    for(int i=t;i<cnt;i+=128){
        int s=snbr[i];
        #pragma unroll
        for(int h=0;h<HEADS;h++){
            float l=ed[d*HEADS+h]+es[s*HEADS+h];
            l = (l>0.f)? l : 0.2f*l;
            salpha[i*HEADS+h]=l;
        }
    }
    __syncthreads();
    if(t<HEADS){
        float mx=-1e30f;
        for(int i=0;i<cnt;i++) mx=fmaxf(mx,salpha[i*HEADS+t]);
        float sm=0.f;
        for(int i=0;i<cnt;i++) sm+=expf(salpha[i*HEADS+t]-mx);
        smax[t]=mx; sinv[t]=1.f/sm;
    }
    __syncthreads();
    for(int i=t;i<cnt*HEADS;i+=128){
        int h=i%HEADS;
        salpha[i]=expf(salpha[i]-smax[h])*sinv[h];
    }
    __syncthreads();
    #pragma unroll
    for(int h=0;h<HEADS;h++){
        float acc=0.f;
        for(int i=0;i<cnt;i++)
            acc += salpha[i*HEADS+h]*feat[(size_t)snbr[i]*(HEADS*FO)+h*FO+t];
        if(MODE==0){
            float v=acc+bias[h*FO+t];
            out[(size_t)d*(HEADS*FO)+h*FO+t]= (v>0.f)? v : expm1f(v);
        } else {
            out[(size_t)d*FO+t]=acc+bias[t]+res[(size_t)d*FO+t]+resb[t];
        }
    }
}

// ---------------- host ----------------
template<typename T> static T* symaddr(const void* sym){
    void* p=nullptr;
    cudaGetSymbolAddress(&p, sym);
    return (T*)p;
}

static void gBig(int M,int N,int K,int KS,const float*A,const float*B,float*dest,
                 const float*bs,cudaStream_t st){
    dim3 g(N/64, M/64, KS);
    if(bs) gemmBig<1><<<g,256,0,st>>>(M,N,K,KS,A,B,dest,bs);
    else   gemmBig<0><<<g,256,0,st>>>(M,N,K,KS,A,B,dest,nullptr);
}
static void g16(int M,int N,int K,const float*A,const float*B,float*C,cudaStream_t st){
    dim3 g(N/64, M/16);
    gemm16<0><<<g,256,0,st>>>(M,N,K,A,B,C,nullptr,nullptr);
}
static void g16_m(int M,int N,int K,const float*A,const float*B,float*C,const int*ipos,const float*xs){
    dim3 g(N/64, M/16);
    gemm16<1><<<g,256>>>(M,N,K,A,B,C,ipos,xs);
}

extern "C" void kernel_launch(void* const* d_in, const int* in_sizes, int n_in,
                              void* d_out, int out_size) {
    const float* x      =(const float*)d_in[0];
    const int*   ei     =(const int*  )d_in[1];
    const float* w0=(const float*)d_in[2],  *b0=(const float*)d_in[3];
    const float* w1=(const float*)d_in[4],  *b1=(const float*)d_in[5];
    const float* w2=(const float*)d_in[6],  *b2=(const float*)d_in[7];
    const float* w3=(const float*)d_in[8],  *b3=(const float*)d_in[9];
    const float* p1=(const float*)d_in[10], *p2=(const float*)d_in[11], *p3=(const float*)d_in[12];
    const float* uw0=(const float*)d_in[13],*ub0=(const float*)d_in[14];
    const float* uw1=(const float*)d_in[15],*ub1=(const float*)d_in[16];
    const float* uw2=(const float*)d_in[17],*ub2=(const float*)d_in[18];
    const float* lng=(const float*)d_in[19],*lnb=(const float*)d_in[20];
    const float* resw=(const float*)d_in[21],*resb=(const float*)d_in[22];
    const float* g1w=(const float*)d_in[23],*g1as=(const float*)d_in[24],*g1ad=(const float*)d_in[25],*g1b=(const float*)d_in[26];
    const float* g2w=(const float*)d_in[27],*g2as=(const float*)d_in[28],*g2ad=(const float*)d_in[29],*g2b=(const float*)d_in[30];

    unsigned char* A0b=symaddr<unsigned char>(g_A0b);
    int* idx0=symaddr<int>(g_idx0); float* val0=symaddr<float>(g_val0); int* cnt0=symaddr<int>(g_cnt0);
    int* idx1=symaddr<int>(g_idx1); float* val1=symaddr<float>(g_val1); int* cnt1=symaddr<int>(g_cnt1);
    float* A2d=symaddr<float>(g_A2d); float* A3d=symaddr<float>(g_A3d);
    float* Rg=symaddr<float>(g_Rg); float* Cg=symaddr<float>(g_Cg);
    float* part=symaddr<float>(g_part);
    float* Y=symaddr<float>(g_Y);   float* S=symaddr<float>(g_S);
    float* x0b=symaddr<float>(g_x0);float* x1b=symaddr<float>(g_x1);
    float* x2b=symaddr<float>(g_x2);float* x3b=symaddr<float>(g_x3);
    float* hb=symaddr<float>(g_hbuf); float* upb=symaddr<float>(g_up);
    float* Ub=symaddr<float>(g_U);  float* Rb=symaddr<float>(g_res);
    float* F1=symaddr<float>(g_feat1); float* GO=symaddr<float>(g_gout);
    float* di0=symaddr<float>(g_dinv0); float* df0=symaddr<float>(g_dfix0);
    float* di1=symaddr<float>(g_dinv1); float* di2=symaddr<float>(g_dinv2); float* di3=symaddr<float>(g_dinv3);
    unsigned long long* keys=symaddr<unsigned long long>(g_keys);
    int* pm1=symaddr<int>(g_perm1); float* vl1=symaddr<float>(g_vals1);
    int* pm2=symaddr<int>(g_perm2); float* vl2=symaddr<float>(g_vals2);
    int* pm3=symaddr<int>(g_perm3); float* vl3=symaddr<float>(g_vals3);
    int* ip1=symaddr<int>(g_ipos1); int* ip2=symaddr<int>(g_ipos2); int* ip3=symaddr<int>(g_ipos3);
    float* ES=symaddr<float>(g_es); float* ED=symaddr<float>(g_ed);
    float* out=(float*)d_out;

    // side stream + events
    static cudaStream_t s2=nullptr;
    static cudaEvent_t ev[8];
    if(!s2){
        cudaStreamCreateWithFlags(&s2,cudaStreamNonBlocking);
        for(int i=0;i<8;i++) cudaEventCreateWithFlags(&ev[i],cudaEventDisableTiming);
    }
    auto FORK=[&](int i){ cudaEventRecord(ev[i],0); cudaStreamWaitEvent(s2,ev[i],0); };
    auto JOIN=[&](int i){ cudaEventRecord(ev[4+i],s2); cudaStreamWaitEvent(0,ev[4+i],0); };

    // ---- build A0 (bytes) + CSR0 ----
    cudaMemsetAsync(A0b,0,(size_t)N0*N0,0);
    k_buildA0<<<cdiv(NE,256),256>>>(ei,(unsigned int*)A0b);
    k_csr0<<<cdiv(N0,8),256>>>(A0b,idx0,val0,cnt0,di0,df0);

    // ---- gcn0 down (x@w0 fused into SpMM) ----
    k_spmm0<<<N0/4,256>>>(idx0,val0,cnt0,di0,df0,x,w0,b0,x0b);

    // ---- pool1 ; [SpGEMM1 || feature GEMM1] ----
    k_scorek<<<cdiv(N0,8),256>>>(N0,x0b,p1,keys);
    k_rank<N0><<<N0/256,256>>>(keys,N1,x0b,pm1,vl1,ip1,hb);
    FORK(0);
    k_spgemm_csr<N1><<<N1,256,0,s2>>>(idx0,val0,cnt0,MAXD0,pm1,ip1,idx1,val1,cnt1,MAXD1,di1);
    g16(N1,FH,FH,hb,w1,Y,0);
    JOIN(0);
    k_spmmf<64><<<cdiv(N1*64,256),256>>>(N1,idx1,val1,cnt1,MAXD1,Y,di1,nullptr,b1,x1b,1);

    // ---- pool2 ; [SpGEMM2(dense) || feature GEMM2] ----
    k_scorek<<<cdiv(N1,8),256>>>(N1,x1b,p2,keys);
    k_rank<N1><<<N1/256,256>>>(keys,N2,x1b,pm2,vl2,ip2,hb);
    FORK(1);
    k_spgemm_dense<N2><<<N2,256,0,s2>>>(idx1,val1,cnt1,MAXD1,pm2,ip2,A2d,di2);
    g16(N2,FH,FH,hb,w2,Y,0);
    JOIN(1);
    gBig(N2,FH,N2,8,A2d,Y,part,di2,0);
    k_kred_gcn<<<cdiv(N2*FH,256),256>>>(N2,FH,8,part,Y,di2,b2,x2b,1);

    // ---- pool3 ; [A3 construction || feature GEMM3] ----
    k_scorek<<<cdiv(N2,8),256>>>(N2,x2b,p3,keys);
    k_rank<N2><<<N2/256,256>>>(keys,N3,x2b,pm3,vl3,ip3,hb);
    FORK(2);
    k_gatherR<<<cdiv(N3*N2,256),256,0,s2>>>(A2d,N2,pm3,N3,Rg);
    k_gatherC<<<cdiv(N3*N2,256),256,0,s2>>>(A2d,N2,pm3,N3,Cg);
    gBig(N3,N3,N2,4,Rg,Cg,part,nullptr,s2);
    k_finishA3red<<<N3,256,0,s2>>>(part,A3d,di3);
    g16(N3,FH,FH,hb,w3,Y,0);
    JOIN(2);
    gBig(N3,FH,N3,8,A3d,Y,part,di3,0);
    k_kred_gcn<<<cdiv(N3*FH,256),256>>>(N3,FH,8,part,Y,di3,b3,x3b,1);

    // ---- up path ----
    g16_m(N2,FH,FH,x2b,uw0,Y,ip3,x3b);
    gBig(N2,FH,N2,8,A2d,Y,part,di2,0);
    k_kred_gcn<<<cdiv(N2*FH,256),256>>>(N2,FH,8,part,Y,di2,ub0,upb,1);

    g16_m(N1,FH,FH,x1b,uw1,Y,ip2,upb);
    k_spmmf<64><<<cdiv(N1*64,256),256>>>(N1,idx1,val1,cnt1,MAXD1,Y,di1,nullptr,ub1,upb,1);

    g16_m(N0,FO,FH,x0b,uw2,Y,ip1,upb);
    k_spmmLN<<<N0/2,256>>>(idx0,val0,cnt0,Y,di0,df0,ub2,lng,lnb,Ub);

    // ---- [residual GEMM || GAT1 chain] ----
    FORK(3);
    gBig(N0,FO,FO,1,Ub,resw,Rb,nullptr,s2);
    gBig(N0,4*FO,FO,1,Ub,g1w,F1,nullptr,0);
    k_esed<<<cdiv(N0,8),256>>>(F1,g1as,g1ad,4,ES,ED);
    k_gat<4,0><<<N0,128>>>(F1,ES,ED,g1b,nullptr,nullptr,GO);
    gBig(N0,FO,4*FO,1,GO,g2w,S,nullptr,0);
    k_esed<<<cdiv(N0,8),256>>>(S,g2as,g2ad,1,ES,ED);
    JOIN(3);
    k_gat<1,1><<<N0,128>>>(S,ES,ED,g2b,Rb,resb,out);
}

// round 16
// speedup vs baseline: 1.5842x; 1.0028x over previous
#include <cuda_runtime.h>
#include <cuda_bf16.h>
#include <math.h>

// ---------------- problem constants ----------------
#define N0 4096
#define N1 2048
#define N2 1024
#define N3 512
#define NE 65536
#define FH 64
#define FO 128
#define MAXD0 128
#define MAXD1 2048

// ---------------- static device scratch ----------------
__device__ unsigned char g_A0b[(size_t)N0*N0];
__device__ int   g_idx0[(size_t)N0*MAXD0]; __device__ float g_val0[(size_t)N0*MAXD0]; __device__ int g_cnt0[N0];
__device__ int   g_idx1[(size_t)N1*MAXD1]; __device__ float g_val1[(size_t)N1*MAXD1]; __device__ int g_cnt1[N1];
__device__ float g_A2d[(size_t)N2*N2];
__device__ float g_A3d[(size_t)N3*N3];
__device__ float g_Rg[(size_t)N3*N2];
__device__ float g_Cg[(size_t)N2*N3];
__device__ float g_part[1<<20];
__device__ float g_Y[(size_t)N0*FO];
__device__ float g_S[(size_t)N0*FO];
__device__ float g_x0[N0*FH], g_x1[N1*FH], g_x2[N2*FH], g_x3[N3*FH];
__device__ float g_hbuf[N0*FH];
__device__ float g_up[N1*FH];
__device__ float g_U[N0*FO];
__device__ float g_res[N0*FO];
__device__ float g_feat1[(size_t)N0*512];
__device__ float g_gout[(size_t)N0*512];
__device__ float g_dinv0[N0], g_dfix0[N0];
__device__ float g_dinv1[N1], g_dinv2[N2], g_dinv3[N3];
__device__ unsigned long long g_keys[N0];
__device__ int   g_perm1[N1]; __device__ float g_vals1[N1];
__device__ int   g_perm2[N2]; __device__ float g_vals2[N2];
__device__ int   g_perm3[N3]; __device__ float g_vals3[N3];
__device__ int   g_ipos1[N0], g_ipos2[N1], g_ipos3[N2];
__device__ float g_es[N0*4], g_ed[N0*4];

static inline int cdiv(int a,int b){return (a+b-1)/b;}

// 64-thread-group key epilogue: given this thread's row value v at column c (c in [0,64)),
// p cached in sp[64], reduce d=sum(v*p[c]) and pn=sum(p[c]^2) over the group; thread c==0
// writes packed key for row r. sred: [8][2] floats per 256-thread block.
__device__ __forceinline__ void key_epilogue(float v,const float* sp,int c,int r,
                                             unsigned long long* keys,float (*sred)[2]){
    float pv=sp[c];
    float d=v*pv, pn=pv*pv;
    #pragma unroll
    for(int o=16;o;o>>=1){ d+=__shfl_xor_sync(0xffffffffu,d,o); pn+=__shfl_xor_sync(0xffffffffu,pn,o); }
    int warpId=threadIdx.x>>5;
    if((threadIdx.x&31)==0){ sred[warpId][0]=d; sred[warpId][1]=pn; }
    __syncthreads();
    if(c==0){
        int g=warpId>>1;
        float dd=sred[2*g][0]+sred[2*g+1][0];
        float pp=sred[2*g][1]+sred[2*g+1][1];
        float key=tanhf(dd*rsqrtf(pp));
        unsigned int f=__float_as_uint(key);
        unsigned int u=f ^ ((f&0x80000000u)? 0xFFFFFFFFu : 0x80000000u);
        keys[r]=((unsigned long long)u<<12) | (unsigned int)(4095-r);
    }
}

// ---------------- gemmBig: 64x64x16, TM=TN=4, optional split-K, optional B row-scale ----------------
template<int BSCALE>
__global__ void __launch_bounds__(256)
gemmBig(int M,int N,int K,int KS,const float* __restrict__ A,const float* __restrict__ B,
        float* __restrict__ dest,const float* __restrict__ bs){
    __shared__ __align__(16) float As[16][64];
    __shared__ __align__(16) float Bs[16][64];
    const int bm=blockIdx.y*64, bn=blockIdx.x*64, z=blockIdx.z;
    const int tid=threadIdx.x;
    const int trow=tid/16, tcol=tid%16;
    const int kchunk=K/KS;
    const int kbeg=z*kchunk, kend=kbeg+kchunk;
    float acc[4][4];
    #pragma unroll
    for(int i=0;i<4;i++)
        #pragma unroll
        for(int j=0;j<4;j++) acc[i][j]=0.f;

    for(int k0=kbeg;k0<kend;k0+=16){
        {
            int m=tid/4, kq=tid%4;
            float4 v=*(const float4*)(A+(size_t)(bm+m)*K+k0+kq*4);
            As[kq*4+0][m]=v.x; As[kq*4+1][m]=v.y; As[kq*4+2][m]=v.z; As[kq*4+3][m]=v.w;
        }
        {
            int k=tid/16, nq=tid%16;
            float4 v=*(const float4*)(B+(size_t)(k0+k)*N+bn+nq*4);
            if(BSCALE){
                float s=bs[k0+k];
                v.x*=s; v.y*=s; v.z*=s; v.w*=s;
            }
            *(float4*)&Bs[k][nq*4]=v;
        }
        __syncthreads();
        #pragma unroll
        for(int kk=0;kk<16;kk++){
            float4 ra=*(const float4*)&As[kk][trow*4];
            float4 rb=*(const float4*)&Bs[kk][tcol*4];
            float a[4]={ra.x,ra.y,ra.z,ra.w};
            float b[4]={rb.x,rb.y,rb.z,rb.w};
            #pragma unroll
            for(int i=0;i<4;i++)
                #pragma unroll
                for(int j=0;j<4;j++) acc[i][j]+=a[i]*b[j];
        }
        __syncthreads();
    }
    float* out=dest+(size_t)z*M*N;
    #pragma unroll
    for(int i=0;i<4;i++){
        int gm=bm+trow*4+i;
        #pragma unroll
        for(int j=0;j<4;j++){
            out[(size_t)gm*N+bn+tcol*4+j]=acc[i][j];
        }
    }
}

// split-K reduce + GCN epilogue; POOL: also emit pool keys (f must be 64)
template<int POOL>
__global__ void k_kred_gcn(int n,int f,int KS,const float* __restrict__ part,
                           const float* __restrict__ Y,const float* __restrict__ di,
                           const float* __restrict__ b,float* __restrict__ out,int relu,
                           const float* __restrict__ p,unsigned long long* __restrict__ keys){
    __shared__ float sp[FH];
    __shared__ float sred[8][2];
    if(POOL && threadIdx.x<FH) sp[threadIdx.x]=p[threadIdx.x];
    if(POOL) __syncthreads();
    int t=blockIdx.x*blockDim.x+threadIdx.x;
    float v=0.f; int r=0;
    if(t<n*f){
        float acc=0.f;
        for(int z=0;z<KS;z++) acc+=part[(size_t)z*n*f+t];
        r=t/f;
        float d=di[r];
        v=d*acc + 2.f*d*d*Y[t] + b[t%f];
        v = relu? fmaxf(v,0.f) : v;
        out[t]=v;
    }
    if(POOL) key_epilogue(v,sp,t%FH,r,keys,sred);
}

// A3 split-K reduce (KS=4) + zero diag + rowsum -> dinv3
__global__ void __launch_bounds__(256) k_finishA3red(const float* __restrict__ part,
                                                     float* __restrict__ A3,float* __restrict__ dinv){
    __shared__ float red[8];
    int r=blockIdx.x, t=threadIdx.x;
    float s=0.f;
    for(int j=t;j<N3;j+=256){
        float acc=part[(size_t)0*N3*N3 + r*N3 + j]
                 +part[(size_t)1*N3*N3 + r*N3 + j]
                 +part[(size_t)2*N3*N3 + r*N3 + j]
                 +part[(size_t)3*N3*N3 + r*N3 + j];
        if(j==r) acc=0.f;
        A3[(size_t)r*N3+j]=acc;
        s+=acc;
    }
    #pragma unroll
    for(int o=16;o;o>>=1) s+=__shfl_xor_sync(0xffffffffu,s,o);
    if((t&31)==0) red[t>>5]=s;
    __syncthreads();
    if(t==0){
        float ss=0.f;
        #pragma unroll
        for(int w=0;w<8;w++) ss+=red[w];
        dinv[r]=rsqrtf(ss+2.f);
    }
}

// ---------------- gemm16: 16x64x16, TM=1,TN=4 ----------------
template<int MERGE>
__global__ void __launch_bounds__(256)
gemm16(int M,int N,int K,const float* __restrict__ Af,const float* __restrict__ B,
       float* __restrict__ C,const int* __restrict__ ipos,const float* __restrict__ xs){
    __shared__ __align__(16) float As[16][16];
    __shared__ __align__(16) float Bs[16][64];
    const int bm=blockIdx.y*16, bn=blockIdx.x*64;
    const int tid=threadIdx.x;
    const int trow=tid/16, tcol=tid%16;
    float acc[4]={0.f,0.f,0.f,0.f};
    for(int k0=0;k0<K;k0+=16){
        {
            int m=tid/16, k=tid%16;
            int gm=bm+m, gk=k0+k;
            float a=Af[(size_t)gm*K+gk];
            if(MERGE){ int j=ipos[gm]; if(j>=0) a+=xs[(size_t)j*K+gk]; }
            As[k][m]=a;
        }
        {
            int k=tid/16, nq=tid%16;
            *(float4*)&Bs[k][nq*4] = *(const float4*)(B+(size_t)(k0+k)*N+bn+nq*4);
        }
        __syncthreads();
        #pragma unroll
        for(int kk=0;kk<16;kk++){
            float a=As[kk][trow];
            float4 rb=*(const float4*)&Bs[kk][tcol*4];
            acc[0]+=a*rb.x; acc[1]+=a*rb.y; acc[2]+=a*rb.z; acc[3]+=a*rb.w;
        }
        __syncthreads();
    }
    int gm=bm+trow;
    #pragma unroll
    for(int j=0;j<4;j++)
        C[(size_t)gm*N+bn+tcol*4+j]=acc[j];
}

// ---------------- graph build ----------------
__global__ void k_buildA0(const int* __restrict__ ei, unsigned int* __restrict__ Aw){
    int e = blockIdx.x*blockDim.x+threadIdx.x;
    if(e<NE){
        int s=ei[e];
        int d=ei[NE+e];
        size_t byteoff=(size_t)d*N0+s;
        atomicAdd(&Aw[byteoff>>2], 1u<<((s&3)*8));
    }
}

__global__ void k_csr0(const unsigned char* __restrict__ Ab,int* __restrict__ idx,float* __restrict__ val,
                       int* __restrict__ cnt,float* __restrict__ dinv,float* __restrict__ dfix){
    int w=(blockIdx.x*blockDim.x+threadIdx.x)>>5;
    int lane=threadIdx.x&31;
    if(w>=N0) return;
    const unsigned int* row=(const unsigned int*)(Ab+(size_t)w*N0);
    int c=0; float rs=0.f;
    for(int base=0;base<N0/4;base+=32){
        unsigned int wv=row[base+lane];
        int colbase=(base+lane)*4;
        #pragma unroll
        for(int b=0;b<4;b++){
            int v=(wv>>(8*b))&255;
            int col=colbase+b;
            bool p=(v!=0)||(col==w);
            unsigned m=__ballot_sync(0xffffffffu,p);
            if(p){
                int off=c+__popc(m&((1u<<lane)-1u));
                idx[(size_t)w*MAXD0+off]=col;
                val[(size_t)w*MAXD0+off]=(float)v;
                rs+=(float)v;
            }
            c+=__popc(m);
        }
    }
    #pragma unroll
    for(int o=16;o;o>>=1) rs+=__shfl_xor_sync(0xffffffffu,rs,o);
    if(lane==0){
        float d=(float)Ab[(size_t)w*N0+w];
        float fx=(d==0.f)?2.f:0.f;
        cnt[w]=c;
        dfix[w]=fx;
        dinv[w]=rsqrtf(rs+fx);
    }
}

// ---------------- level0 fused SpMM (+ pool1 keys) ----------------
__global__ void __launch_bounds__(256) k_spmm0(const int* __restrict__ idx,const float* __restrict__ val,
                        const int* __restrict__ cnt,const float* __restrict__ dinv,
                        const float* __restrict__ dfix,
                        const float* __restrict__ x,const float* __restrict__ w,
                        const float* __restrict__ b,float* __restrict__ out,
                        const float* __restrict__ p,unsigned long long* __restrict__ keys){
    __shared__ float sw[3*FH];
    __shared__ float sp[FH];
    __shared__ float sred[8][2];
    if(threadIdx.x<3*FH) sw[threadIdx.x]=w[threadIdx.x];
    if(threadIdx.x<FH) sp[threadIdx.x]=p[threadIdx.x];
    __syncthreads();
    int r = blockIdx.x*4 + threadIdx.x/FH;
    int c = threadIdx.x%FH;
    int cn=cnt[r];
    const int* ip=idx+(size_t)r*MAXD0;
    const float* vp=val+(size_t)r*MAXD0;
    float w0c=sw[c], w1c=sw[FH+c], w2c=sw[2*FH+c];
    float acc=0.f;
    for(int e=0;e<cn;e++){
        int s=ip[e];
        const float* xr=x+(size_t)s*3;
        float ys=dinv[s]*(xr[0]*w0c+xr[1]*w1c+xr[2]*w2c);
        acc += vp[e]*ys;
    }
    float di=dinv[r];
    const float* xr=x+(size_t)r*3;
    float ysS=di*(xr[0]*w0c+xr[1]*w1c+xr[2]*w2c);
    float v = fmaxf(di*acc + dfix[r]*di*ysS + b[c], 0.f);
    out[(size_t)r*FH+c]=v;
    key_epilogue(v,sp,c,r,keys,sred);
}

// ---------------- CSR SpMM + GCN epilogue; POOL emits keys (F must be 64) ----------------
template<int F,int POOL>
__global__ void k_spmmf(int n,const int* __restrict__ idx,const float* __restrict__ val,
                        const int* __restrict__ cnt,int maxd,
                        const float* __restrict__ Y,const float* __restrict__ dinv,
                        const float* __restrict__ dfix,const float* __restrict__ b,
                        float* __restrict__ out,int relu,
                        const float* __restrict__ p,unsigned long long* __restrict__ keys){
    __shared__ float sp[FH];
    __shared__ float sred[8][2];
    if(POOL && threadIdx.x<FH) sp[threadIdx.x]=p[threadIdx.x];
    if(POOL) __syncthreads();
    int r = blockIdx.x*(256/F) + threadIdx.x/F;
    int c = threadIdx.x%F;
    float v=0.f;
    if(r<n){
        int cn=cnt[r];
        const int* ip=idx+(size_t)r*maxd;
        const float* vp=val+(size_t)r*maxd;
        float acc=0.f;
        for(int e=0;e<cn;e++){
            int s=ip[e];
            acc += vp[e]*dinv[s]*Y[(size_t)s*F+c];
        }
        float fx = dfix? dfix[r] : 2.0f;
        float di = dinv[r];
        v = di*acc + fx*di*di*Y[(size_t)r*F+c] + b[c];
        v = relu? fmaxf(v,0.f) : v;
        out[(size_t)r*F+c]=v;
    }
    if(POOL) key_epilogue(v,sp,c,r,keys,sred);
}

// CSR SpMM (F=128) + LayerNorm fused
__global__ void __launch_bounds__(256) k_spmmLN(const int* __restrict__ idx,const float* __restrict__ val,
                        const int* __restrict__ cnt,
                        const float* __restrict__ Y,const float* __restrict__ dinv,
                        const float* __restrict__ dfix,const float* __restrict__ b,
                        const float* __restrict__ lg,const float* __restrict__ lb,
                        float* __restrict__ u){
    __shared__ float sh[256];
    int r = blockIdx.x*2 + threadIdx.x/128;
    int c = threadIdx.x%128;
    int base = threadIdx.x & 128;
    int cn=cnt[r];
    const int* ip=idx+(size_t)r*MAXD0;
    const float* vp=val+(size_t)r*MAXD0;
    float acc=0.f;
    for(int e=0;e<cn;e++){
        int s=ip[e];
        acc += vp[e]*dinv[s]*Y[(size_t)s*FO+c];
    }
    float di=dinv[r];
    float v = di*acc + dfix[r]*di*di*Y[(size_t)r*FO+c] + b[c];
    sh[threadIdx.x]=v; __syncthreads();
    for(int o=64;o;o>>=1){ if(c<o) sh[base+c]+=sh[base+c+o]; __syncthreads(); }
    float mu=sh[base]/128.f; __syncthreads();
    float d=v-mu;
    sh[threadIdx.x]=d*d; __syncthreads();
    for(int o=64;o;o>>=1){ if(c<o) sh[base+c]+=sh[base+c+o]; __syncthreads(); }
    float var=sh[base]/128.f;
    u[(size_t)r*FO+c]=d*rsqrtf(var+1e-6f)*lg[c]+lb[c];
}

// ---------------- pool rank (multi-SM, exact jax.lax.top_k order) ----------------
template<int N>
__global__ void __launch_bounds__(256) k_rank(const unsigned long long* __restrict__ keys,int k,
                        const float* __restrict__ x,int* __restrict__ perm,float* __restrict__ vals,
                        int* __restrict__ ipos,float* __restrict__ h){
    __shared__ unsigned long long sk[N];
    int t=threadIdx.x;
    for(int i=t;i<N;i+=256) sk[i]=keys[i];
    __syncthreads();
    int r=blockIdx.x*256+t;
    unsigned long long my=sk[r];
    int rank=0;
    #pragma unroll 8
    for(int j=0;j<N;j++) rank += (sk[j]>my);
    if(rank<k){
        unsigned int u=(unsigned int)(my>>12);
        unsigned int f=u ^ ((u&0x80000000u)? 0x80000000u : 0xFFFFFFFFu);
        float key=__uint_as_float(f);
        perm[rank]=r; vals[rank]=key; ipos[r]=rank;
        const float4* xr=(const float4*)(x+(size_t)r*FH);
        float4* hr=(float4*)(h+(size_t)rank*FH);
        #pragma unroll
        for(int q=0;q<FH/4;q++){
            float4 v=xr[q];
            v.x*=key; v.y*=key; v.z*=key; v.w*=key;
            hr[q]=v;
        }
    } else {
        ipos[r]=-1;
    }
}

// ---------------- SpGEMM level1 (CSR out, input HAS diag entries) ----------------
template<int NCOL>
__global__ void __launch_bounds__(256) k_spgemm_csr(
        const int* __restrict__ inIdx,const float* __restrict__ inVal,const int* __restrict__ inCnt,int inMaxd,
        const int* __restrict__ perm,const int* __restrict__ ipos,
        int* __restrict__ outIdx,float* __restrict__ outVal,int* __restrict__ outCnt,int outMaxd,
        float* __restrict__ dinv){
    __shared__ float acc[NCOL];
    int i=blockIdx.x, t=threadIdx.x;
    for(int j=t;j<NCOL;j+=256) acc[j]=0.f;
    __syncthreads();
    int r0=perm[i];
    int cr=inCnt[r0];
    const int* rip=inIdx+(size_t)r0*inMaxd;
    const float* rvp=inVal+(size_t)r0*inMaxd;
    int warp=t>>5, lane=t&31;
    for(int e=warp;e<cr;e+=8){
        int k=rip[e];
        float rv=rvp[e] + ((k==r0)?1.f:0.f);
        int ck=inCnt[k];
        const int* kip=inIdx+(size_t)k*inMaxd;
        const float* kvp=inVal+(size_t)k*inMaxd;
        for(int f=lane;f<ck;f+=32){
            int s=kip[f];
            float cv=kvp[f] + ((s==k)?1.f:0.f);
            int j=ipos[s];
            if(j>=0) atomicAdd(&acc[j], rv*cv);
        }
    }
    __syncthreads();
    if(t==0) acc[i]=0.f;
    __syncthreads();
    if(warp==0){
        int c=0; float rs=0.f;
        for(int base=0;base<NCOL;base+=32){
            int j=base+lane;
            float v=acc[j];
            bool p=(v!=0.f);
            unsigned m=__ballot_sync(0xffffffffu,p);
            if(p){
                int off=c+__popc(m&((1u<<lane)-1u));
                outIdx[(size_t)i*outMaxd+off]=j;
                outVal[(size_t)i*outMaxd+off]=v;
                rs+=v;
            }
            c+=__popc(m);
        }
        #pragma unroll
        for(int o=16;o;o>>=1) rs+=__shfl_xor_sync(0xffffffffu,rs,o);
        if(lane==0){ outCnt[i]=c; dinv[i]=rsqrtf(rs+2.f); }
    }
}

// ---------------- SpGEMM level2 (dense out, input CSR has NO diag) ----------------
template<int NCOL>
__global__ void __launch_bounds__(256) k_spgemm_dense(
        const int* __restrict__ inIdx,const float* __restrict__ inVal,const int* __restrict__ inCnt,int inMaxd,
        const int* __restrict__ perm,const int* __restrict__ ipos,
        float* __restrict__ outD,float* __restrict__ dinv){
    __shared__ float acc[NCOL];
    __shared__ float red[8];
    int i=blockIdx.x, t=threadIdx.x;
    for(int j=t;j<NCOL;j+=256) acc[j]=0.f;
    __syncthreads();
    int r0=perm[i];
    int cr=inCnt[r0];
    int total=cr+1;
    const int* rip=inIdx+(size_t)r0*inMaxd;
    const float* rvp=inVal+(size_t)r0*inMaxd;
    int warp=t>>5, lane=t&31;
    for(int e=warp;e<total;e+=8){
        int k; float rv;
        if(e<cr){ k=rip[e]; rv=rvp[e]; }
        else    { k=r0; rv=1.f; }
        int ck=inCnt[k];
        const int* kip=inIdx+(size_t)k*inMaxd;
        const float* kvp=inVal+(size_t)k*inMaxd;
        int tot2=ck+1;
        for(int f=lane;f<tot2;f+=32){
            int s; float cv;
            if(f<ck){ s=kip[f]; cv=kvp[f]; }
            else    { s=k; cv=1.f; }
            int j=ipos[s];
            if(j>=0) atomicAdd(&acc[j], rv*cv);
        }
    }
    __syncthreads();
    if(t==0) acc[i]=0.f;
    __syncthreads();
    float rs=0.f;
    for(int j=t;j<NCOL;j+=256){ rs+=acc[j]; outD[(size_t)i*NCOL+j]=acc[j]; }
    #pragma unroll
    for(int o=16;o;o>>=1) rs+=__shfl_xor_sync(0xffffffffu,rs,o);
    if(lane==0) red[warp]=rs;
    __syncthreads();
    if(t==0){
        float s=0.f;
        #pragma unroll
        for(int w=0;w<8;w++) s+=red[w];
        dinv[i]=rsqrtf(s+2.f);
    }
}

// ---------------- level-3 gathers (fused R+C) ----------------
__global__ void k_gatherRC(const float* __restrict__ A,int n,const int* __restrict__ perm,int m,
                           float* __restrict__ R,float* __restrict__ C){
    size_t tot=(size_t)m*n;
    size_t t=(size_t)blockIdx.x*blockDim.x+threadIdx.x;
    if(t<tot){
        int i=(int)(t/n), k=(int)(t%n);
        int pi=perm[i];
        R[t]=A[(size_t)pi*n+k] + ((k==pi)?1.f:0.f);
    } else if(t<2*tot){
        size_t u=t-tot;
        int k=(int)(u/m), j=(int)(u%m);
        int pj=perm[j];
        C[u]=A[(size_t)k*n+pj] + ((k==pj)?1.f:0.f);
    }
}

// ---------------- GAT ----------------
__global__ void k_esed(const float* __restrict__ feat,const float* __restrict__ asrc,const float* __restrict__ adst,int heads,float* __restrict__ es,float* __restrict__ ed){
    int w=(blockIdx.x*blockDim.x+threadIdx.x)>>5;
    int lane=threadIdx.x&31;
    if(w>=N0) return;
    for(int h=0;h<heads;h++){
        float a=0.f,d=0.f;
        for(int c=lane;c<FO;c+=32){
            float f=feat[(size_t)w*(heads*FO)+h*FO+c];
            a+=f*asrc[h*FO+c];
            d+=f*adst[h*FO+c];
        }
        #pragma unroll
        for(int o=16;o;o>>=1){ a+=__shfl_xor_sync(0xffffffffu,a,o); d+=__shfl_xor_sync(0xffffffffu,d,o); }
        if(lane==0){ es[w*heads+h]=a; ed[w*heads+h]=d; }
    }
}

template<int HEADS,int MODE>
__global__ void __launch_bounds__(128) k_gat(const float* __restrict__ feat,const float* __restrict__ es,const float* __restrict__ ed,
                                             const float* __restrict__ bias,const float* __restrict__ res,const float* __restrict__ resb,
                                             float* __restrict__ out){
    __shared__ int snbr[MAXD0];
    __shared__ float salpha[MAXD0*HEADS];
    __shared__ float smax[HEADS], sinv[HEADS];
    int d=blockIdx.x, t=threadIdx.x;
    int cnt=g_cnt0[d];
    for(int i=t;i<cnt;i+=128) snbr[i]=g_idx0[(size_t)d*MAXD0+i];
    __syncthreads();
    for(int i=t;i<cnt;i+=128){
        int s=snbr[i];
        #pragma unroll
        for(int h=0;h<HEADS;h++){
            float l=ed[d*HEADS+h]+es[s*HEADS+h];
            l = (l>0.f)? l : 0.2f*l;
            salpha[i*HEADS+h]=l;
        }
    }
    __syncthreads();
    if(t<HEADS){
        float mx=-1e30f;
        for(int i=0;i<cnt;i++) mx=fmaxf(mx,salpha[i*HEADS+t]);
        float sm=0.f;
        for(int i=0;i<cnt;i++) sm+=expf(salpha[i*HEADS+t]-mx);
        smax[t]=mx; sinv[t]=1.f/sm;
    }
    __syncthreads();
    for(int i=t;i<cnt*HEADS;i+=128){
        int h=i%HEADS;
        salpha[i]=expf(salpha[i]-smax[h])*sinv[h];
    }
    __syncthreads();
    #pragma unroll
    for(int h=0;h<HEADS;h++){
        float acc=0.f;
        for(int i=0;i<cnt;i++)
            acc += salpha[i*HEADS+h]*feat[(size_t)snbr[i]*(HEADS*FO)+h*FO+t];
        if(MODE==0){
            float v=acc+bias[h*FO+t];
            out[(size_t)d*(HEADS*FO)+h*FO+t]= (v>0.f)? v : expm1f(v);
        } else {
            out[(size_t)d*FO+t]=acc+bias[t]+res[(size_t)d*FO+t]+resb[t];
        }
    }
}

// ---------------- host ----------------
template<typename T> static T* symaddr(const void* sym){
    void* p=nullptr;
    cudaGetSymbolAddress(&p, sym);
    return (T*)p;
}

static void gBig(int M,int N,int K,int KS,const float*A,const float*B,float*dest,
                 const float*bs,cudaStream_t st){
    dim3 g(N/64, M/64, KS);
    if(bs) gemmBig<1><<<g,256,0,st>>>(M,N,K,KS,A,B,dest,bs);
    else   gemmBig<0><<<g,256,0,st>>>(M,N,K,KS,A,B,dest,nullptr);
}
static void g16(int M,int N,int K,const float*A,const float*B,float*C,cudaStream_t st){
    dim3 g(N/64, M/16);
    gemm16<0><<<g,256,0,st>>>(M,N,K,A,B,C,nullptr,nullptr);
}
static void g16_m(int M,int N,int K,const float*A,const float*B,float*C,const int*ipos,const float*xs){
    dim3 g(N/64, M/16);
    gemm16<1><<<g,256>>>(M,N,K,A,B,C,ipos,xs);
}

extern "C" void kernel_launch(void* const* d_in, const int* in_sizes, int n_in,
                              void* d_out, int out_size) {
    const float* x      =(const float*)d_in[0];
    const int*   ei     =(const int*  )d_in[1];
    const float* w0=(const float*)d_in[2],  *b0=(const float*)d_in[3];
    const float* w1=(const float*)d_in[4],  *b1=(const float*)d_in[5];
    const float* w2=(const float*)d_in[6],  *b2=(const float*)d_in[7];
    const float* w3=(const float*)d_in[8],  *b3=(const float*)d_in[9];
    const float* p1=(const float*)d_in[10], *p2=(const float*)d_in[11], *p3=(const float*)d_in[12];
    const float* uw0=(const float*)d_in[13],*ub0=(const float*)d_in[14];
    const float* uw1=(const float*)d_in[15],*ub1=(const float*)d_in[16];
    const float* uw2=(const float*)d_in[17],*ub2=(const float*)d_in[18];
    const float* lng=(const float*)d_in[19],*lnb=(const float*)d_in[20];
    const float* resw=(const float*)d_in[21],*resb=(const float*)d_in[22];
    const float* g1w=(const float*)d_in[23],*g1as=(const float*)d_in[24],*g1ad=(const float*)d_in[25],*g1b=(const float*)d_in[26];
    const float* g2w=(const float*)d_in[27],*g2as=(const float*)d_in[28],*g2ad=(const float*)d_in[29],*g2b=(const float*)d_in[30];

    unsigned char* A0b=symaddr<unsigned char>(g_A0b);
    int* idx0=symaddr<int>(g_idx0); float* val0=symaddr<float>(g_val0); int* cnt0=symaddr<int>(g_cnt0);
    int* idx1=symaddr<int>(g_idx1); float* val1=symaddr<float>(g_val1); int* cnt1=symaddr<int>(g_cnt1);
    float* A2d=symaddr<float>(g_A2d); float* A3d=symaddr<float>(g_A3d);
    float* Rg=symaddr<float>(g_Rg); float* Cg=symaddr<float>(g_Cg);
    float* part=symaddr<float>(g_part);
    float* Y=symaddr<float>(g_Y);   float* S=symaddr<float>(g_S);
    float* x0b=symaddr<float>(g_x0);float* x1b=symaddr<float>(g_x1);
    float* x2b=symaddr<float>(g_x2);float* x3b=symaddr<float>(g_x3);
    float* hb=symaddr<float>(g_hbuf); float* upb=symaddr<float>(g_up);
    float* Ub=symaddr<float>(g_U);  float* Rb=symaddr<float>(g_res);
    float* F1=symaddr<float>(g_feat1); float* GO=symaddr<float>(g_gout);
    float* di0=symaddr<float>(g_dinv0); float* df0=symaddr<float>(g_dfix0);
    float* di1=symaddr<float>(g_dinv1); float* di2=symaddr<float>(g_dinv2); float* di3=symaddr<float>(g_dinv3);
    unsigned long long* keys=symaddr<unsigned long long>(g_keys);
    int* pm1=symaddr<int>(g_perm1); float* vl1=symaddr<float>(g_vals1);
    int* pm2=symaddr<int>(g_perm2); float* vl2=symaddr<float>(g_vals2);
    int* pm3=symaddr<int>(g_perm3); float* vl3=symaddr<float>(g_vals3);
    int* ip1=symaddr<int>(g_ipos1); int* ip2=symaddr<int>(g_ipos2); int* ip3=symaddr<int>(g_ipos3);
    float* ES=symaddr<float>(g_es); float* ED=symaddr<float>(g_ed);
    float* out=(float*)d_out;

    // side stream + events
    static cudaStream_t s2=nullptr;
    static cudaEvent_t ev[8];
    if(!s2){
        cudaStreamCreateWithFlags(&s2,cudaStreamNonBlocking);
        for(int i=0;i<8;i++) cudaEventCreateWithFlags(&ev[i],cudaEventDisableTiming);
    }
    auto FORK=[&](int i){ cudaEventRecord(ev[i],0); cudaStreamWaitEvent(s2,ev[i],0); };
    auto JOIN=[&](int i){ cudaEventRecord(ev[4+i],s2); cudaStreamWaitEvent(0,ev[4+i],0); };

    // ---- build A0 (bytes) + CSR0 ----
    cudaMemsetAsync(A0b,0,(size_t)N0*N0,0);
    k_buildA0<<<cdiv(NE,256),256>>>(ei,(unsigned int*)A0b);
    k_csr0<<<cdiv(N0,8),256>>>(A0b,idx0,val0,cnt0,di0,df0);

    // ---- gcn0 down (x@w0 fused into SpMM, + pool1 keys) ----
    k_spmm0<<<N0/4,256>>>(idx0,val0,cnt0,di0,df0,x,w0,b0,x0b,p1,keys);

    // ---- pool1 rank ; [SpGEMM1 || feature GEMM1] ----
    k_rank<N0><<<N0/256,256>>>(keys,N1,x0b,pm1,vl1,ip1,hb);
    FORK(0);
    k_spgemm_csr<N1><<<N1,256,0,s2>>>(idx0,val0,cnt0,MAXD0,pm1,ip1,idx1,val1,cnt1,MAXD1,di1);
    g16(N1,FH,FH,hb,w1,Y,0);
    JOIN(0);
    k_spmmf<64,1><<<cdiv(N1*64,256),256>>>(N1,idx1,val1,cnt1,MAXD1,Y,di1,nullptr,b1,x1b,1,p2,keys);

    // ---- pool2 rank ; [SpGEMM2(dense) || feature GEMM2] ----
    k_rank<N1><<<N1/256,256>>>(keys,N2,x1b,pm2,vl2,ip2,hb);
    FORK(1);
    k_spgemm_dense<N2><<<N2,256,0,s2>>>(idx1,val1,cnt1,MAXD1,pm2,ip2,A2d,di2);
    g16(N2,FH,FH,hb,w2,Y,0);
    JOIN(1);
    gBig(N2,FH,N2,8,A2d,Y,part,di2,0);
    k_kred_gcn<1><<<cdiv(N2*FH,256),256>>>(N2,FH,8,part,Y,di2,b2,x2b,1,p3,keys);

    // ---- pool3 rank ; [A3 construction || feature GEMM3] ----
    k_rank<N2><<<N2/256,256>>>(keys,N3,x2b,pm3,vl3,ip3,hb);
    FORK(2);
    k_gatherRC<<<cdiv(2*N3*N2,256),256,0,s2>>>(A2d,N2,pm3,N3,Rg,Cg);
    gBig(N3,N3,N2,4,Rg,Cg,part,nullptr,s2);
    k_finishA3red<<<N3,256,0,s2>>>(part,A3d,di3);
    g16(N3,FH,FH,hb,w3,Y,0);
    JOIN(2);
    gBig(N3,FH,N3,8,A3d,Y,part,di3,0);
    k_kred_gcn<0><<<cdiv(N3*FH,256),256>>>(N3,FH,8,part,Y,di3,b3,x3b,1,nullptr,nullptr);

    // ---- up path ----
    g16_m(N2,FH,FH,x2b,uw0,Y,ip3,x3b);
    gBig(N2,FH,N2,8,A2d,Y,part,di2,0);
    k_kred_gcn<0><<<cdiv(N2*FH,256),256>>>(N2,FH,8,part,Y,di2,ub0,upb,1,nullptr,nullptr);

    g16_m(N1,FH,FH,x1b,uw1,Y,ip2,upb);
    k_spmmf<64,0><<<cdiv(N1*64,256),256>>>(N1,idx1,val1,cnt1,MAXD1,Y,di1,nullptr,ub1,upb,1,nullptr,nullptr);

    g16_m(N0,FO,FH,x0b,uw2,Y,ip1,upb);
    k_spmmLN<<<N0/2,256>>>(idx0,val0,cnt0,Y,di0,df0,ub2,lng,lnb,Ub);

    // ---- [residual GEMM || GAT1 chain] ----
    FORK(3);
    gBig(N0,FO,FO,1,Ub,resw,Rb,nullptr,s2);
    gBig(N0,4*FO,FO,1,Ub,g1w,F1,nullptr,0);
    k_esed<<<cdiv(N0,8),256>>>(F1,g1as,g1ad,4,ES,ED);
    k_gat<4,0><<<N0,128>>>(F1,ES,ED,g1b,nullptr,nullptr,GO);
    gBig(N0,FO,4*FO,1,GO,g2w,S,nullptr,0);
    k_esed<<<cdiv(N0,8),256>>>(S,g2as,g2ad,1,ES,ED);
    JOIN(3);
    k_gat<1,1><<<N0,128>>>(S,ES,ED,g2b,Rb,resb,out);
}

// round 17
// speedup vs baseline: 1.7246x; 1.0886x over previous
#include <cuda_runtime.h>
#include <cuda_bf16.h>
#include <math.h>

// ---------------- problem constants ----------------
#define N0 4096
#define N1 2048
#define N2 1024
#define N3 512
#define NE 65536
#define FH 64
#define FO 128
#define MAXD0 128
#define MAXD1 2048

// ---------------- static device scratch ----------------
__device__ unsigned char g_A0b[(size_t)N0*N0];
__device__ int   g_idx0[(size_t)N0*MAXD0]; __device__ float g_val0[(size_t)N0*MAXD0]; __device__ int g_cnt0[N0];
__device__ int   g_idx1[(size_t)N1*MAXD1]; __device__ float g_val1[(size_t)N1*MAXD1]; __device__ int g_cnt1[N1];
__device__ float g_A2d[(size_t)N2*N2];
__device__ float g_A3d[(size_t)N3*N3];
__device__ float g_Rg[(size_t)N3*N2];
__device__ float g_Cg[(size_t)N2*N3];
__device__ float g_part[1<<20];
__device__ float g_Y[(size_t)N0*FO];
__device__ float g_S[(size_t)N0*FO];
__device__ float g_x0[N0*FH], g_x1[N1*FH], g_x2[N2*FH], g_x3[N3*FH];
__device__ float g_hbuf[N0*FH];
__device__ float g_up[N1*FH];
__device__ float g_U[N0*FO];
__device__ float g_res[N0*FO];
__device__ float g_feat1[(size_t)N0*512];
__device__ float g_gout[(size_t)N0*512];
__device__ float g_dinv0[N0], g_dfix0[N0];
__device__ float g_dinv1[N1], g_dinv2[N2], g_dinv3[N3];
__device__ unsigned long long g_keys[N0];
__device__ int   g_perm1[N1]; __device__ float g_vals1[N1];
__device__ int   g_perm2[N2]; __device__ float g_vals2[N2];
__device__ int   g_perm3[N3]; __device__ float g_vals3[N3];
__device__ int   g_ipos1[N0], g_ipos2[N1], g_ipos3[N2];
__device__ float g_es[N0*4], g_ed[N0*4];

static inline int cdiv(int a,int b){return (a+b-1)/b;}

// 64-thread-group key epilogue (c in [0,64)); thread c==0 writes packed key for row r.
__device__ __forceinline__ void key_epilogue(float v,const float* sp,int c,int r,
                                             unsigned long long* keys,float (*sred)[2]){
    float pv=sp[c];
    float d=v*pv, pn=pv*pv;
    #pragma unroll
    for(int o=16;o;o>>=1){ d+=__shfl_xor_sync(0xffffffffu,d,o); pn+=__shfl_xor_sync(0xffffffffu,pn,o); }
    int warpId=threadIdx.x>>5;
    if((threadIdx.x&31)==0){ sred[warpId][0]=d; sred[warpId][1]=pn; }
    __syncthreads();
    if(c==0){
        int g=warpId>>1;
        float dd=sred[2*g][0]+sred[2*g+1][0];
        float pp=sred[2*g][1]+sred[2*g+1][1];
        float key=tanhf(dd*rsqrtf(pp));
        unsigned int f=__float_as_uint(key);
        unsigned int u=f ^ ((f&0x80000000u)? 0xFFFFFFFFu : 0x80000000u);
        keys[r]=((unsigned long long)u<<12) | (unsigned int)(4095-r);
    }
}

// ---------------- gemmBig: 64x64x16, TM=TN=4, optional split-K, optional B row-scale ----------------
template<int BSCALE>
__global__ void __launch_bounds__(256)
gemmBig(int M,int N,int K,int KS,const float* __restrict__ A,const float* __restrict__ B,
        float* __restrict__ dest,const float* __restrict__ bs){
    __shared__ __align__(16) float As[16][64];
    __shared__ __align__(16) float Bs[16][64];
    const int bm=blockIdx.y*64, bn=blockIdx.x*64, z=blockIdx.z;
    const int tid=threadIdx.x;
    const int trow=tid/16, tcol=tid%16;
    const int kchunk=K/KS;
    const int kbeg=z*kchunk, kend=kbeg+kchunk;
    float acc[4][4];
    #pragma unroll
    for(int i=0;i<4;i++)
        #pragma unroll
        for(int j=0;j<4;j++) acc[i][j]=0.f;

    for(int k0=kbeg;k0<kend;k0+=16){
        {
            int m=tid/4, kq=tid%4;
            float4 v=*(const float4*)(A+(size_t)(bm+m)*K+k0+kq*4);
            As[kq*4+0][m]=v.x; As[kq*4+1][m]=v.y; As[kq*4+2][m]=v.z; As[kq*4+3][m]=v.w;
        }
        {
            int k=tid/16, nq=tid%16;
            float4 v=*(const float4*)(B+(size_t)(k0+k)*N+bn+nq*4);
            if(BSCALE){
                float s=bs[k0+k];
                v.x*=s; v.y*=s; v.z*=s; v.w*=s;
            }
            *(float4*)&Bs[k][nq*4]=v;
        }
        __syncthreads();
        #pragma unroll
        for(int kk=0;kk<16;kk++){
            float4 ra=*(const float4*)&As[kk][trow*4];
            float4 rb=*(const float4*)&Bs[kk][tcol*4];
            float a[4]={ra.x,ra.y,ra.z,ra.w};
            float b[4]={rb.x,rb.y,rb.z,rb.w};
            #pragma unroll
            for(int i=0;i<4;i++)
                #pragma unroll
                for(int j=0;j<4;j++) acc[i][j]+=a[i]*b[j];
        }
        __syncthreads();
    }
    float* out=dest+(size_t)z*M*N;
    #pragma unroll
    for(int i=0;i<4;i++){
        int gm=bm+trow*4+i;
        #pragma unroll
        for(int j=0;j<4;j++){
            out[(size_t)gm*N+bn+tcol*4+j]=acc[i][j];
        }
    }
}

// split-K reduce + GCN epilogue; POOL: also emit pool keys (f must be 64)
template<int POOL>
__global__ void k_kred_gcn(int n,int f,int KS,const float* __restrict__ part,
                           const float* __restrict__ Y,const float* __restrict__ di,
                           const float* __restrict__ b,float* __restrict__ out,int relu,
                           const float* __restrict__ p,unsigned long long* __restrict__ keys){
    __shared__ float sp[FH];
    __shared__ float sred[8][2];
    if(POOL && threadIdx.x<FH) sp[threadIdx.x]=p[threadIdx.x];
    if(POOL) __syncthreads();
    int t=blockIdx.x*blockDim.x+threadIdx.x;
    float v=0.f; int r=0;
    if(t<n*f){
        float acc=0.f;
        for(int z=0;z<KS;z++) acc+=part[(size_t)z*n*f+t];
        r=t/f;
        float d=di[r];
        v=d*acc + 2.f*d*d*Y[t] + b[t%f];
        v = relu? fmaxf(v,0.f) : v;
        out[t]=v;
    }
    if(POOL) key_epilogue(v,sp,t%FH,r,keys,sred);
}

// A3 split-K reduce (KS=4) + zero diag + rowsum -> dinv3
__global__ void __launch_bounds__(256) k_finishA3red(const float* __restrict__ part,
                                                     float* __restrict__ A3,float* __restrict__ dinv){
    __shared__ float red[8];
    int r=blockIdx.x, t=threadIdx.x;
    float s=0.f;
    for(int j=t;j<N3;j+=256){
        float acc=part[(size_t)0*N3*N3 + r*N3 + j]
                 +part[(size_t)1*N3*N3 + r*N3 + j]
                 +part[(size_t)2*N3*N3 + r*N3 + j]
                 +part[(size_t)3*N3*N3 + r*N3 + j];
        if(j==r) acc=0.f;
        A3[(size_t)r*N3+j]=acc;
        s+=acc;
    }
    #pragma unroll
    for(int o=16;o;o>>=1) s+=__shfl_xor_sync(0xffffffffu,s,o);
    if((t&31)==0) red[t>>5]=s;
    __syncthreads();
    if(t==0){
        float ss=0.f;
        #pragma unroll
        for(int w=0;w<8;w++) ss+=red[w];
        dinv[r]=rsqrtf(ss+2.f);
    }
}

// ---------------- gemm16: 16x64x16, TM=1,TN=4 ----------------
template<int MERGE>
__global__ void __launch_bounds__(256)
gemm16(int M,int N,int K,const float* __restrict__ Af,const float* __restrict__ B,
       float* __restrict__ C,const int* __restrict__ ipos,const float* __restrict__ xs){
    __shared__ __align__(16) float As[16][16];
    __shared__ __align__(16) float Bs[16][64];
    const int bm=blockIdx.y*16, bn=blockIdx.x*64;
    const int tid=threadIdx.x;
    const int trow=tid/16, tcol=tid%16;
    float acc[4]={0.f,0.f,0.f,0.f};
    for(int k0=0;k0<K;k0+=16){
        {
            int m=tid/16, k=tid%16;
            int gm=bm+m, gk=k0+k;
            float a=Af[(size_t)gm*K+gk];
            if(MERGE){ int j=ipos[gm]; if(j>=0) a+=xs[(size_t)j*K+gk]; }
            As[k][m]=a;
        }
        {
            int k=tid/16, nq=tid%16;
            *(float4*)&Bs[k][nq*4] = *(const float4*)(B+(size_t)(k0+k)*N+bn+nq*4);
        }
        __syncthreads();
        #pragma unroll
        for(int kk=0;kk<16;kk++){
            float a=As[kk][trow];
            float4 rb=*(const float4*)&Bs[kk][tcol*4];
            acc[0]+=a*rb.x; acc[1]+=a*rb.y; acc[2]+=a*rb.z; acc[3]+=a*rb.w;
        }
        __syncthreads();
    }
    int gm=bm+trow;
    #pragma unroll
    for(int j=0;j<4;j++)
        C[(size_t)gm*N+bn+tcol*4+j]=acc[j];
}

// ---------------- graph build ----------------
__global__ void k_buildA0(const int* __restrict__ ei, unsigned int* __restrict__ Aw){
    int e = blockIdx.x*blockDim.x+threadIdx.x;
    if(e<NE){
        int s=ei[e];
        int d=ei[NE+e];
        size_t byteoff=(size_t)d*N0+s;
        atomicAdd(&Aw[byteoff>>2], 1u<<((s&3)*8));
    }
}

__global__ void k_csr0(const unsigned char* __restrict__ Ab,int* __restrict__ idx,float* __restrict__ val,
                       int* __restrict__ cnt,float* __restrict__ dinv,float* __restrict__ dfix){
    int w=(blockIdx.x*blockDim.x+threadIdx.x)>>5;
    int lane=threadIdx.x&31;
    if(w>=N0) return;
    const unsigned int* row=(const unsigned int*)(Ab+(size_t)w*N0);
    int c=0; float rs=0.f;
    for(int base=0;base<N0/4;base+=32){
        unsigned int wv=row[base+lane];
        int colbase=(base+lane)*4;
        #pragma unroll
        for(int b=0;b<4;b++){
            int v=(wv>>(8*b))&255;
            int col=colbase+b;
            bool p=(v!=0)||(col==w);
            unsigned m=__ballot_sync(0xffffffffu,p);
            if(p){
                int off=c+__popc(m&((1u<<lane)-1u));
                idx[(size_t)w*MAXD0+off]=col;
                val[(size_t)w*MAXD0+off]=(float)v;
                rs+=(float)v;
            }
            c+=__popc(m);
        }
    }
    #pragma unroll
    for(int o=16;o;o>>=1) rs+=__shfl_xor_sync(0xffffffffu,rs,o);
    if(lane==0){
        float d=(float)Ab[(size_t)w*N0+w];
        float fx=(d==0.f)?2.f:0.f;
        cnt[w]=c;
        dfix[w]=fx;
        dinv[w]=rsqrtf(rs+fx);
    }
}

// ---------------- level0 fused SpMM (+ pool1 keys) ----------------
__global__ void __launch_bounds__(256) k_spmm0(const int* __restrict__ idx,const float* __restrict__ val,
                        const int* __restrict__ cnt,const float* __restrict__ dinv,
                        const float* __restrict__ dfix,
                        const float* __restrict__ x,const float* __restrict__ w,
                        const float* __restrict__ b,float* __restrict__ out,
                        const float* __restrict__ p,unsigned long long* __restrict__ keys){
    __shared__ float sw[3*FH];
    __shared__ float sp[FH];
    __shared__ float sred[8][2];
    if(threadIdx.x<3*FH) sw[threadIdx.x]=w[threadIdx.x];
    if(threadIdx.x<FH) sp[threadIdx.x]=p[threadIdx.x];
    __syncthreads();
    int r = blockIdx.x*4 + threadIdx.x/FH;
    int c = threadIdx.x%FH;
    int cn=cnt[r];
    const int* ip=idx+(size_t)r*MAXD0;
    const float* vp=val+(size_t)r*MAXD0;
    float w0c=sw[c], w1c=sw[FH+c], w2c=sw[2*FH+c];
    float acc=0.f;
    for(int e=0;e<cn;e++){
        int s=ip[e];
        const float* xr=x+(size_t)s*3;
        float ys=dinv[s]*(xr[0]*w0c+xr[1]*w1c+xr[2]*w2c);
        acc += vp[e]*ys;
    }
    float di=dinv[r];
    const float* xr=x+(size_t)r*3;
    float ysS=di*(xr[0]*w0c+xr[1]*w1c+xr[2]*w2c);
    float v = fmaxf(di*acc + dfix[r]*di*ysS + b[c], 0.f);
    out[(size_t)r*FH+c]=v;
    key_epilogue(v,sp,c,r,keys,sred);
}

// ---------------- CSR SpMM + GCN epilogue; POOL emits keys (F must be 64) ----------------
template<int F,int POOL>
__global__ void k_spmmf(int n,const int* __restrict__ idx,const float* __restrict__ val,
                        const int* __restrict__ cnt,int maxd,
                        const float* __restrict__ Y,const float* __restrict__ dinv,
                        const float* __restrict__ dfix,const float* __restrict__ b,
                        float* __restrict__ out,int relu,
                        const float* __restrict__ p,unsigned long long* __restrict__ keys){
    __shared__ float sp[FH];
    __shared__ float sred[8][2];
    if(POOL && threadIdx.x<FH) sp[threadIdx.x]=p[threadIdx.x];
    if(POOL) __syncthreads();
    int r = blockIdx.x*(256/F) + threadIdx.x/F;
    int c = threadIdx.x%F;
    float v=0.f;
    if(r<n){
        int cn=cnt[r];
        const int* ip=idx+(size_t)r*maxd;
        const float* vp=val+(size_t)r*maxd;
        float acc=0.f;
        for(int e=0;e<cn;e++){
            int s=ip[e];
            acc += vp[e]*dinv[s]*Y[(size_t)s*F+c];
        }
        float fx = dfix? dfix[r] : 2.0f;
        float di = dinv[r];
        v = di*acc + fx*di*di*Y[(size_t)r*F+c] + b[c];
        v = relu? fmaxf(v,0.f) : v;
        out[(size_t)r*F+c]=v;
    }
    if(POOL) key_epilogue(v,sp,c,r,keys,sred);
}

// CSR SpMM (F=128) + LayerNorm fused
__global__ void __launch_bounds__(256) k_spmmLN(const int* __restrict__ idx,const float* __restrict__ val,
                        const int* __restrict__ cnt,
                        const float* __restrict__ Y,const float* __restrict__ dinv,
                        const float* __restrict__ dfix,const float* __restrict__ b,
                        const float* __restrict__ lg,const float* __restrict__ lb,
                        float* __restrict__ u){
    __shared__ float sh[256];
    int r = blockIdx.x*2 + threadIdx.x/128;
    int c = threadIdx.x%128;
    int base = threadIdx.x & 128;
    int cn=cnt[r];
    const int* ip=idx+(size_t)r*MAXD0;
    const float* vp=val+(size_t)r*MAXD0;
    float acc=0.f;
    for(int e=0;e<cn;e++){
        int s=ip[e];
        acc += vp[e]*dinv[s]*Y[(size_t)s*FO+c];
    }
    float di=dinv[r];
    float v = di*acc + dfix[r]*di*di*Y[(size_t)r*FO+c] + b[c];
    sh[threadIdx.x]=v; __syncthreads();
    for(int o=64;o;o>>=1){ if(c<o) sh[base+c]+=sh[base+c+o]; __syncthreads(); }
    float mu=sh[base]/128.f; __syncthreads();
    float d=v-mu;
    sh[threadIdx.x]=d*d; __syncthreads();
    for(int o=64;o;o>>=1){ if(c<o) sh[base+c]+=sh[base+c+o]; __syncthreads(); }
    float var=sh[base]/128.f;
    u[(size_t)r*FO+c]=d*rsqrtf(var+1e-6f)*lg[c]+lb[c];
}

// ---------------- pool rank (multi-SM, 16 threads per row, exact jax.lax.top_k order) ----------------
template<int N>
__global__ void __launch_bounds__(256) k_rank(const unsigned long long* __restrict__ keys,int k,
                        const float* __restrict__ x,int* __restrict__ perm,float* __restrict__ vals,
                        int* __restrict__ ipos,float* __restrict__ h){
    constexpr int TPR=16;                 // threads per row
    constexpr int ROWS=256/TPR;           // 16 rows per block
    __shared__ unsigned long long sk[N];
    int t=threadIdx.x;
    for(int i=t;i<N;i+=256) sk[i]=keys[i];
    __syncthreads();
    int r=blockIdx.x*ROWS + t/TPR;
    int sub=t%TPR;
    unsigned long long my=sk[r];
    int rank=0;
    const int CH=N/TPR;
    int j0=sub*CH;
    #pragma unroll 8
    for(int j=0;j<CH;j++) rank += (sk[j0+j]>my);
    #pragma unroll
    for(int o=TPR/2;o;o>>=1) rank += __shfl_down_sync(0xffffffffu, rank, o, TPR);
    if(sub==0){
        if(rank<k){
            unsigned int u=(unsigned int)(my>>12);
            unsigned int f=u ^ ((u&0x80000000u)? 0x80000000u : 0xFFFFFFFFu);
            float key=__uint_as_float(f);
            perm[rank]=r; vals[rank]=key; ipos[r]=rank;
            const float4* xr=(const float4*)(x+(size_t)r*FH);
            float4* hr=(float4*)(h+(size_t)rank*FH);
            #pragma unroll
            for(int q=0;q<FH/4;q++){
                float4 v=xr[q];
                v.x*=key; v.y*=key; v.z*=key; v.w*=key;
                hr[q]=v;
            }
        } else {
            ipos[r]=-1;
        }
    }
}

// ---------------- SpGEMM level1 (CSR out, input HAS diag entries) ----------------
template<int NCOL>
__global__ void __launch_bounds__(256) k_spgemm_csr(
        const int* __restrict__ inIdx,const float* __restrict__ inVal,const int* __restrict__ inCnt,int inMaxd,
        const int* __restrict__ perm,const int* __restrict__ ipos,
        int* __restrict__ outIdx,float* __restrict__ outVal,int* __restrict__ outCnt,int outMaxd,
        float* __restrict__ dinv){
    __shared__ float acc[NCOL];
    int i=blockIdx.x, t=threadIdx.x;
    for(int j=t;j<NCOL;j+=256) acc[j]=0.f;
    __syncthreads();
    int r0=perm[i];
    int cr=inCnt[r0];
    const int* rip=inIdx+(size_t)r0*inMaxd;
    const float* rvp=inVal+(size_t)r0*inMaxd;
    int warp=t>>5, lane=t&31;
    for(int e=warp;e<cr;e+=8){
        int k=rip[e];
        float rv=rvp[e] + ((k==r0)?1.f:0.f);
        int ck=inCnt[k];
        const int* kip=inIdx+(size_t)k*inMaxd;
        const float* kvp=inVal+(size_t)k*inMaxd;
        for(int f=lane;f<ck;f+=32){
            int s=kip[f];
            float cv=kvp[f] + ((s==k)?1.f:0.f);
            int j=ipos[s];
            if(j>=0) atomicAdd(&acc[j], rv*cv);
        }
    }
    __syncthreads();
    if(t==0) acc[i]=0.f;
    __syncthreads();
    if(warp==0){
        int c=0; float rs=0.f;
        for(int base=0;base<NCOL;base+=32){
            int j=base+lane;
            float v=acc[j];
            bool p=(v!=0.f);
            unsigned m=__ballot_sync(0xffffffffu,p);
            if(p){
                int off=c+__popc(m&((1u<<lane)-1u));
                outIdx[(size_t)i*outMaxd+off]=j;
                outVal[(size_t)i*outMaxd+off]=v;
                rs+=v;
            }
            c+=__popc(m);
        }
        #pragma unroll
        for(int o=16;o;o>>=1) rs+=__shfl_xor_sync(0xffffffffu,rs,o);
        if(lane==0){ outCnt[i]=c; dinv[i]=rsqrtf(rs+2.f); }
    }
}

// ---------------- SpGEMM level2 (dense out, input CSR has NO diag) ----------------
template<int NCOL>
__global__ void __launch_bounds__(256) k_spgemm_dense(
        const int* __restrict__ inIdx,const float* __restrict__ inVal,const int* __restrict__ inCnt,int inMaxd,
        const int* __restrict__ perm,const int* __restrict__ ipos,
        float* __restrict__ outD,float* __restrict__ dinv){
    __shared__ float acc[NCOL];
    __shared__ float red[8];
    int i=blockIdx.x, t=threadIdx.x;
    for(int j=t;j<NCOL;j+=256) acc[j]=0.f;
    __syncthreads();
    int r0=perm[i];
    int cr=inCnt[r0];
    int total=cr+1;
    const int* rip=inIdx+(size_t)r0*inMaxd;
    const float* rvp=inVal+(size_t)r0*inMaxd;
    int warp=t>>5, lane=t&31;
    for(int e=warp;e<total;e+=8){
        int k; float rv;
        if(e<cr){ k=rip[e]; rv=rvp[e]; }
        else    { k=r0; rv=1.f; }
        int ck=inCnt[k];
        const int* kip=inIdx+(size_t)k*inMaxd;
        const float* kvp=inVal+(size_t)k*inMaxd;
        int tot2=ck+1;
        for(int f=lane;f<tot2;f+=32){
            int s; float cv;
            if(f<ck){ s=kip[f]; cv=kvp[f]; }
            else    { s=k; cv=1.f; }
            int j=ipos[s];
            if(j>=0) atomicAdd(&acc[j], rv*cv);
        }
    }
    __syncthreads();
    if(t==0) acc[i]=0.f;
    __syncthreads();
    float rs=0.f;
    for(int j=t;j<NCOL;j+=256){ rs+=acc[j]; outD[(size_t)i*NCOL+j]=acc[j]; }
    #pragma unroll
    for(int o=16;o;o>>=1) rs+=__shfl_xor_sync(0xffffffffu,rs,o);
    if(lane==0) red[warp]=rs;
    __syncthreads();
    if(t==0){
        float s=0.f;
        #pragma unroll
        for(int w=0;w<8;w++) s+=red[w];
        dinv[i]=rsqrtf(s+2.f);
    }
}

// ---------------- level-3 gathers (fused R+C) ----------------
__global__ void k_gatherRC(const float* __restrict__ A,int n,const int* __restrict__ perm,int m,
                           float* __restrict__ R,float* __restrict__ C){
    size_t tot=(size_t)m*n;
    size_t t=(size_t)blockIdx.x*blockDim.x+threadIdx.x;
    if(t<tot){
        int i=(int)(t/n), k=(int)(t%n);
        int pi=perm[i];
        R[t]=A[(size_t)pi*n+k] + ((k==pi)?1.f:0.f);
    } else if(t<2*tot){
        size_t u=t-tot;
        int k=(int)(u/m), j=(int)(u%m);
        int pj=perm[j];
        C[u]=A[(size_t)k*n+pj] + ((k==pj)?1.f:0.f);
    }
}

// ---------------- GAT ----------------
__global__ void k_esed(const float* __restrict__ feat,const float* __restrict__ asrc,const float* __restrict__ adst,int heads,float* __restrict__ es,float* __restrict__ ed){
    int w=(blockIdx.x*blockDim.x+threadIdx.x)>>5;
    int lane=threadIdx.x&31;
    if(w>=N0) return;
    for(int h=0;h<heads;h++){
        float a=0.f,d=0.f;
        for(int c=lane;c<FO;c+=32){
            float f=feat[(size_t)w*(heads*FO)+h*FO+c];
            a+=f*asrc[h*FO+c];
            d+=f*adst[h*FO+c];
        }
        #pragma unroll
        for(int o=16;o;o>>=1){ a+=__shfl_xor_sync(0xffffffffu,a,o); d+=__shfl_xor_sync(0xffffffffu,d,o); }
        if(lane==0){ es[w*heads+h]=a; ed[w*heads+h]=d; }
    }
}

template<int HEADS,int MODE>
__global__ void __launch_bounds__(128) k_gat(const float* __restrict__ feat,const float* __restrict__ es,const float* __restrict__ ed,
                                             const float* __restrict__ bias,const float* __restrict__ res,const float* __restrict__ resb,
                                             float* __restrict__ out){
    __shared__ int snbr[MAXD0];
    __shared__ float salpha[MAXD0*HEADS];
    __shared__ float smax[HEADS], sinv[HEADS];
    int d=blockIdx.x, t=threadIdx.x;
    int cnt=g_cnt0[d];
    for(int i=t;i<cnt;i+=128) snbr[i]=g_idx0[(size_t)d*MAXD0+i];
    __syncthreads();
    for(int i=t;i<cnt;i+=128){
        int s=snbr[i];
        #pragma unroll
        for(int h=0;h<HEADS;h++){
            float l=ed[d*HEADS+h]+es[s*HEADS+h];
            l = (l>0.f)? l : 0.2f*l;
            salpha[i*HEADS+h]=l;
        }
    }
    __syncthreads();
    if(t<HEADS){
        float mx=-1e30f;
        for(int i=0;i<cnt;i++) mx=fmaxf(mx,salpha[i*HEADS+t]);
        float sm=0.f;
        for(int i=0;i<cnt;i++) sm+=expf(salpha[i*HEADS+t]-mx);
        smax[t]=mx; sinv[t]=1.f/sm;
    }
    __syncthreads();
    for(int i=t;i<cnt*HEADS;i+=128){
        int h=i%HEADS;
        salpha[i]=expf(salpha[i]-smax[h])*sinv[h];
    }
    __syncthreads();
    #pragma unroll
    for(int h=0;h<HEADS;h++){
        float acc=0.f;
        for(int i=0;i<cnt;i++)
            acc += salpha[i*HEADS+h]*feat[(size_t)snbr[i]*(HEADS*FO)+h*FO+t];
        if(MODE==0){
            float v=acc+bias[h*FO+t];
            out[(size_t)d*(HEADS*FO)+h*FO+t]= (v>0.f)? v : expm1f(v);
        } else {
            out[(size_t)d*FO+t]=acc+bias[t]+res[(size_t)d*FO+t]+resb[t];
        }
    }
}

// ---------------- host ----------------
template<typename T> static T* symaddr(const void* sym){
    void* p=nullptr;
    cudaGetSymbolAddress(&p, sym);
    return (T*)p;
}

static void gBig(int M,int N,int K,int KS,const float*A,const float*B,float*dest,
                 const float*bs,cudaStream_t st){
    dim3 g(N/64, M/64, KS);
    if(bs) gemmBig<1><<<g,256,0,st>>>(M,N,K,KS,A,B,dest,bs);
    else   gemmBig<0><<<g,256,0,st>>>(M,N,K,KS,A,B,dest,nullptr);
}
static void g16(int M,int N,int K,const float*A,const float*B,float*C,cudaStream_t st){
    dim3 g(N/64, M/16);
    gemm16<0><<<g,256,0,st>>>(M,N,K,A,B,C,nullptr,nullptr);
}
static void g16_m(int M,int N,int K,const float*A,const float*B,float*C,const int*ipos,const float*xs){
    dim3 g(N/64, M/16);
    gemm16<1><<<g,256>>>(M,N,K,A,B,C,ipos,xs);
}

extern "C" void kernel_launch(void* const* d_in, const int* in_sizes, int n_in,
                              void* d_out, int out_size) {
    const float* x      =(const float*)d_in[0];
    const int*   ei     =(const int*  )d_in[1];
    const float* w0=(const float*)d_in[2],  *b0=(const float*)d_in[3];
    const float* w1=(const float*)d_in[4],  *b1=(const float*)d_in[5];
    const float* w2=(const float*)d_in[6],  *b2=(const float*)d_in[7];
    const float* w3=(const float*)d_in[8],  *b3=(const float*)d_in[9];
    const float* p1=(const float*)d_in[10], *p2=(const float*)d_in[11], *p3=(const float*)d_in[12];
    const float* uw0=(const float*)d_in[13],*ub0=(const float*)d_in[14];
    const float* uw1=(const float*)d_in[15],*ub1=(const float*)d_in[16];
    const float* uw2=(const float*)d_in[17],*ub2=(const float*)d_in[18];
    const float* lng=(const float*)d_in[19],*lnb=(const float*)d_in[20];
    const float* resw=(const float*)d_in[21],*resb=(const float*)d_in[22];
    const float* g1w=(const float*)d_in[23],*g1as=(const float*)d_in[24],*g1ad=(const float*)d_in[25],*g1b=(const float*)d_in[26];
    const float* g2w=(const float*)d_in[27],*g2as=(const float*)d_in[28],*g2ad=(const float*)d_in[29],*g2b=(const float*)d_in[30];

    unsigned char* A0b=symaddr<unsigned char>(g_A0b);
    int* idx0=symaddr<int>(g_idx0); float* val0=symaddr<float>(g_val0); int* cnt0=symaddr<int>(g_cnt0);
    int* idx1=symaddr<int>(g_idx1); float* val1=symaddr<float>(g_val1); int* cnt1=symaddr<int>(g_cnt1);
    float* A2d=symaddr<float>(g_A2d); float* A3d=symaddr<float>(g_A3d);
    float* Rg=symaddr<float>(g_Rg); float* Cg=symaddr<float>(g_Cg);
    float* part=symaddr<float>(g_part);
    float* Y=symaddr<float>(g_Y);   float* S=symaddr<float>(g_S);
    float* x0b=symaddr<float>(g_x0);float* x1b=symaddr<float>(g_x1);
    float* x2b=symaddr<float>(g_x2);float* x3b=symaddr<float>(g_x3);
    float* hb=symaddr<float>(g_hbuf); float* upb=symaddr<float>(g_up);
    float* Ub=symaddr<float>(g_U);  float* Rb=symaddr<float>(g_res);
    float* F1=symaddr<float>(g_feat1); float* GO=symaddr<float>(g_gout);
    float* di0=symaddr<float>(g_dinv0); float* df0=symaddr<float>(g_dfix0);
    float* di1=symaddr<float>(g_dinv1); float* di2=symaddr<float>(g_dinv2); float* di3=symaddr<float>(g_dinv3);
    unsigned long long* keys=symaddr<unsigned long long>(g_keys);
    int* pm1=symaddr<int>(g_perm1); float* vl1=symaddr<float>(g_vals1);
    int* pm2=symaddr<int>(g_perm2); float* vl2=symaddr<float>(g_vals2);
    int* pm3=symaddr<int>(g_perm3); float* vl3=symaddr<float>(g_vals3);
    int* ip1=symaddr<int>(g_ipos1); int* ip2=symaddr<int>(g_ipos2); int* ip3=symaddr<int>(g_ipos3);
    float* ES=symaddr<float>(g_es); float* ED=symaddr<float>(g_ed);
    float* out=(float*)d_out;

    // side stream + events
    static cudaStream_t s2=nullptr;
    static cudaEvent_t ev[8];
    if(!s2){
        cudaStreamCreateWithFlags(&s2,cudaStreamNonBlocking);
        for(int i=0;i<8;i++) cudaEventCreateWithFlags(&ev[i],cudaEventDisableTiming);
    }
    auto FORK=[&](int i){ cudaEventRecord(ev[i],0); cudaStreamWaitEvent(s2,ev[i],0); };
    auto JOIN=[&](int i){ cudaEventRecord(ev[4+i],s2); cudaStreamWaitEvent(0,ev[4+i],0); };

    // ---- build A0 (bytes) + CSR0 ----
    cudaMemsetAsync(A0b,0,(size_t)N0*N0,0);
    k_buildA0<<<cdiv(NE,256),256>>>(ei,(unsigned int*)A0b);
    k_csr0<<<cdiv(N0,8),256>>>(A0b,idx0,val0,cnt0,di0,df0);

    // ---- gcn0 down (x@w0 fused into SpMM, + pool1 keys) ----
    k_spmm0<<<N0/4,256>>>(idx0,val0,cnt0,di0,df0,x,w0,b0,x0b,p1,keys);

    // ---- pool1 rank ; [SpGEMM1 || feature GEMM1] ----
    k_rank<N0><<<N0/16,256>>>(keys,N1,x0b,pm1,vl1,ip1,hb);
    FORK(0);
    k_spgemm_csr<N1><<<N1,256,0,s2>>>(idx0,val0,cnt0,MAXD0,pm1,ip1,idx1,val1,cnt1,MAXD1,di1);
    g16(N1,FH,FH,hb,w1,Y,0);
    JOIN(0);
    k_spmmf<64,1><<<cdiv(N1*64,256),256>>>(N1,idx1,val1,cnt1,MAXD1,Y,di1,nullptr,b1,x1b,1,p2,keys);

    // ---- pool2 rank ; [SpGEMM2(dense) || feature GEMM2] ----
    k_rank<N1><<<N1/16,256>>>(keys,N2,x1b,pm2,vl2,ip2,hb);
    FORK(1);
    k_spgemm_dense<N2><<<N2,256,0,s2>>>(idx1,val1,cnt1,MAXD1,pm2,ip2,A2d,di2);
    g16(N2,FH,FH,hb,w2,Y,0);
    JOIN(1);
    gBig(N2,FH,N2,8,A2d,Y,part,di2,0);
    k_kred_gcn<1><<<cdiv(N2*FH,256),256>>>(N2,FH,8,part,Y,di2,b2,x2b,1,p3,keys);

    // ---- pool3 rank ; [A3 construction || feature GEMM3] ----
    k_rank<N2><<<N2/16,256>>>(keys,N3,x2b,pm3,vl3,ip3,hb);
    FORK(2);
    k_gatherRC<<<cdiv(2*N3*N2,256),256,0,s2>>>(A2d,N2,pm3,N3,Rg,Cg);
    gBig(N3,N3,N2,4,Rg,Cg,part,nullptr,s2);
    k_finishA3red<<<N3,256,0,s2>>>(part,A3d,di3);
    g16(N3,FH,FH,hb,w3,Y,0);
    JOIN(2);
    gBig(N3,FH,N3,8,A3d,Y,part,di3,0);
    k_kred_gcn<0><<<cdiv(N3*FH,256),256>>>(N3,FH,8,part,Y,di3,b3,x3b,1,nullptr,nullptr);

    // ---- up path ----
    g16_m(N2,FH,FH,x2b,uw0,Y,ip3,x3b);
    gBig(N2,FH,N2,8,A2d,Y,part,di2,0);
    k_kred_gcn<0><<<cdiv(N2*FH,256),256>>>(N2,FH,8,part,Y,di2,ub0,upb,1,nullptr,nullptr);

    g16_m(N1,FH,FH,x1b,uw1,Y,ip2,upb);
    k_spmmf<64,0><<<cdiv(N1*64,256),256>>>(N1,idx1,val1,cnt1,MAXD1,Y,di1,nullptr,ub1,upb,1,nullptr,nullptr);

    g16_m(N0,FO,FH,x0b,uw2,Y,ip1,upb);
    k_spmmLN<<<N0/2,256>>>(idx0,val0,cnt0,Y,di0,df0,ub2,lng,lnb,Ub);

    // ---- [residual GEMM || GAT1 chain] ----
    FORK(3);
    gBig(N0,FO,FO,1,Ub,resw,Rb,nullptr,s2);
    gBig(N0,4*FO,FO,1,Ub,g1w,F1,nullptr,0);
    k_esed<<<cdiv(N0,8),256>>>(F1,g1as,g1ad,4,ES,ED);
    k_gat<4,0><<<N0,128>>>(F1,ES,ED,g1b,nullptr,nullptr,GO);
    gBig(N0,FO,4*FO,1,GO,g2w,S,nullptr,0);
    k_esed<<<cdiv(N0,8),256>>>(S,g2as,g2ad,1,ES,ED);
    JOIN(3);
    k_gat<1,1><<<N0,128>>>(S,ES,ED,g2b,Rb,resb,out);
}